// round 5
// baseline (speedup 1.0000x reference)
#include <cuda_runtime.h>
#include <cuda_bf16.h>
#include <stdint.h>

#define NUM_SEQS 4
#define SEQ_LEN  4096
#define NTOK     16384
#define HIDDEN   2048
#define CONV_DIM 2048
#define KSZ      4
#define BCX_COLS 6144
#define KDIM     2048

// ---------------- scratch (static device globals; allocation-free) ----------
__device__ float g_bcx[(size_t)NTOK * BCX_COLS];
__device__ int8_t g_qah[(size_t)NTOK * KDIM];       // hidden hi plane
__device__ int8_t g_qal[(size_t)NTOK * KDIM];       // hidden lo plane
__device__ int8_t g_qbh[(size_t)BCX_COLS * KDIM];   // w_in hi
__device__ int8_t g_qbl[(size_t)BCX_COLS * KDIM];   // w_in lo
__device__ __nv_bfloat16 g_wouth[(size_t)HIDDEN * KDIM];
__device__ __nv_bfloat16 g_woutl[(size_t)HIDDEN * KDIM];
__device__ __nv_bfloat16 g_yh[(size_t)NTOK * KDIM];
__device__ __nv_bfloat16 g_yl[(size_t)NTOK * KDIM];
__device__ unsigned g_maxbits[2];

// ---------------- ptx helpers (baseline ISA only) ----------------------------
__device__ __forceinline__ uint32_t smem_u32(const void* p) {
    uint32_t a;
    asm("{ .reg .u64 t; cvta.to.shared.u64 t, %1; cvt.u32.u64 %0, t; }" : "=r"(a) : "l"(p));
    return a;
}
__device__ __forceinline__ void cpasync16(uint32_t dst, const void* src) {
    asm volatile("cp.async.cg.shared.global [%0], [%1], 16;" :: "r"(dst), "l"(src));
}
__device__ __forceinline__ void cp_commit() { asm volatile("cp.async.commit_group;" ::: "memory"); }
__device__ __forceinline__ void cp_wait0()  { asm volatile("cp.async.wait_group 0;" ::: "memory"); }
__device__ __forceinline__ void cp_wait1()  { asm volatile("cp.async.wait_group 1;" ::: "memory"); }

#define LDSM4(r, addr)                                                      \
    asm volatile("ldmatrix.sync.aligned.m8n8.x4.shared.b16 {%0,%1,%2,%3}, [%4];" \
        : "=r"((r)[0]), "=r"((r)[1]), "=r"((r)[2]), "=r"((r)[3]) : "r"(addr))

#define MMA16816(acc, a, b0r, b1r)                                          \
    asm volatile("mma.sync.aligned.m16n8k16.row.col.f32.bf16.bf16.f32 "     \
        "{%0,%1,%2,%3}, {%4,%5,%6,%7}, {%8,%9}, {%0,%1,%2,%3};"             \
        : "+f"((acc)[0]), "+f"((acc)[1]), "+f"((acc)[2]), "+f"((acc)[3])    \
        : "r"((a)[0]), "r"((a)[1]), "r"((a)[2]), "r"((a)[3]),               \
          "r"(b0r), "r"(b1r))

#define MMAS8(acc, a, b0r, b1r)                                             \
    asm volatile("mma.sync.aligned.m16n8k32.row.col.s32.s8.s8.s32 "         \
        "{%0,%1,%2,%3}, {%4,%5,%6,%7}, {%8,%9}, {%0,%1,%2,%3};"             \
        : "+r"((acc)[0]), "+r"((acc)[1]), "+r"((acc)[2]), "+r"((acc)[3])    \
        : "r"((a)[0]), "r"((a)[1]), "r"((a)[2]), "r"((a)[3]),               \
          "r"(b0r), "r"(b1r))

__device__ __forceinline__ uint32_t swz128(uint32_t off) { return off ^ ((off >> 3) & 0x70); }

// ========================= int8 GEMM1 =======================================
// C[M,N] = s_ab * (16384*hh + 128*(hl+lh)),  A,B int8 hi/lo planes, K-major
// CTA 128x128, warp tile 32x64 (warps 4x2), BK=128 int8 (128B rows), 3 stages
#define IBK 128
#define INC (KDIM / IBK)            // 16
#define IOFF_AH 0
#define IOFF_AL 16384
#define IOFF_BH 32768
#define IOFF_BL 49152
#define ISTAGE  65536
#define IGSMEM  (3 * ISTAGE)        // 192KB

__global__ __launch_bounds__(256, 1)
void gemm_s8x3(const int8_t* __restrict__ Ah, const int8_t* __restrict__ Al,
               const int8_t* __restrict__ Bh, const int8_t* __restrict__ Bl,
               float* __restrict__ C, int ldC)
{
    extern __shared__ char smem[];
    const uint32_t sbase = smem_u32(smem);
    const int tid  = threadIdx.x;
    const int lane = tid & 31;
    const int wid  = tid >> 5;
    const int wm   = wid >> 1;       // 0..3 (32 rows each)
    const int wn   = wid & 1;        // 0..1 (64 cols each)
    const int m0 = blockIdx.y * 128;
    const int n0 = blockIdx.x * 128;

    const int8_t* gA[2] = { Ah + (size_t)m0 * KDIM, Al + (size_t)m0 * KDIM };
    const int8_t* gB[2] = { Bh + (size_t)n0 * KDIM, Bl + (size_t)n0 * KDIM };

    // ldmatrix address components
    uint32_t aRow[2], aXor[2];
#pragma unroll
    for (int mt = 0; mt < 2; mt++) {
        uint32_t r = wm * 32 + mt * 16 + (lane & 15);
        aRow[mt] = r * 128;
        aXor[mt] = (aRow[mt] >> 3) & 0x70;
    }
    const uint32_t aKb = (lane >> 4);
    uint32_t bRow[4], bXor[4];
#pragma unroll
    for (int p = 0; p < 4; p++) {
        uint32_t r = wn * 64 + p * 16 + (lane & 7) + ((lane >> 4) << 3);
        bRow[p] = r * 128;
        bXor[p] = (bRow[p] >> 3) & 0x70;
    }
    const uint32_t bKb = ((lane >> 3) & 1);

    int acc_hh[2][8][4], acc_m[2][8][4];
#pragma unroll
    for (int i = 0; i < 2; i++)
#pragma unroll
        for (int j = 0; j < 8; j++)
#pragma unroll
            for (int q = 0; q < 4; q++) { acc_hh[i][j][q] = 0; acc_m[i][j][q] = 0; }

    // stage filler: 4 sub-tiles x 1024 16B-units => 16 LDGSTS/thread
    auto load_chunk = [&](int c, int st) {
        const uint32_t stg = sbase + st * ISTAGE;
        const int koff = c * IBK;
        const uint32_t offs[4] = { IOFF_AH, IOFF_AL, IOFF_BH, IOFF_BL };
        const int8_t* gp[4] = { gA[0], gA[1], gB[0], gB[1] };
#pragma unroll
        for (int m = 0; m < 4; m++) {
#pragma unroll
            for (int p = 0; p < 4; p++) {
                int u = p * 256 + tid;
                int r = u >> 3, kb = u & 7;
                cpasync16(stg + offs[m] + swz128(r * 128 + kb * 16),
                          gp[m] + (size_t)r * KDIM + koff + kb * 16);
            }
        }
    };

    // prologue: stages 0,1
    load_chunk(0, 0); cp_commit();
    load_chunk(1, 1); cp_commit();
    cp_wait1();
    __syncthreads();

    for (int ch = 0; ch < INC; ch++) {
        if (ch + 2 < INC) load_chunk(ch + 2, (ch + 2) % 3);
        cp_commit();

        const uint32_t stg = sbase + (ch % 3) * ISTAGE;
#pragma unroll
        for (int q = 0; q < 4; q++) {            // 4 k32 steps per 128B chunk
            const uint32_t kb_a = (q * 2 + aKb) * 16;
            const uint32_t kb_b = (q * 2 + bKb) * 16;
            uint32_t ah[2][4], al[2][4], bh[4][4], bl[4][4];
#pragma unroll
            for (int mt = 0; mt < 2; mt++) {
                uint32_t ad = stg + aRow[mt] + (kb_a ^ aXor[mt]);
                LDSM4(ah[mt], ad + IOFF_AH);
                LDSM4(al[mt], ad + IOFF_AL);
            }
#pragma unroll
            for (int p = 0; p < 4; p++) {
                uint32_t bd = stg + bRow[p] + (kb_b ^ bXor[p]);
                LDSM4(bh[p], bd + IOFF_BH);
                LDSM4(bl[p], bd + IOFF_BL);
            }
#pragma unroll
            for (int mt = 0; mt < 2; mt++) {
#pragma unroll
                for (int nt = 0; nt < 8; nt++) {
                    const int p = nt >> 1, bi = (nt & 1) * 2;
                    MMAS8(acc_hh[mt][nt], ah[mt], bh[p][bi], bh[p][bi + 1]);
                    MMAS8(acc_m[mt][nt],  ah[mt], bl[p][bi], bl[p][bi + 1]);
                    MMAS8(acc_m[mt][nt],  al[mt], bh[p][bi], bh[p][bi + 1]);
                }
            }
        }
        cp_wait1();
        __syncthreads();
    }

    // epilogue
    float mA = __uint_as_float(g_maxbits[0]); if (mA == 0.f) mA = 1.f;
    float mB = __uint_as_float(g_maxbits[1]); if (mB == 0.f) mB = 1.f;
    float s_ab = (mA / 16256.0f) * (mB / 16256.0f);
    float sh = s_ab * 16384.0f, sm = s_ab * 128.0f;

    const int rw = m0 + wm * 32 + (lane >> 2);
    const int cw = n0 + wn * 64 + (lane & 3) * 2;
#pragma unroll
    for (int mt = 0; mt < 2; mt++) {
#pragma unroll
        for (int nt = 0; nt < 8; nt++) {
            const int* hh = acc_hh[mt][nt];
            const int* mm = acc_m[mt][nt];
            float* p0 = C + (size_t)(rw + mt * 16) * ldC + cw + nt * 8;
            float* p1 = C + (size_t)(rw + mt * 16 + 8) * ldC + cw + nt * 8;
            *(float2*)p0 = make_float2(sh * (float)hh[0] + sm * (float)mm[0],
                                       sh * (float)hh[1] + sm * (float)mm[1]);
            *(float2*)p1 = make_float2(sh * (float)hh[2] + sm * (float)mm[2],
                                       sh * (float)hh[3] + sm * (float)mm[3]);
        }
    }
}

// ========================= bf16x3 GEMM2 (proven R4 kernel) ==================
#define BM 128
#define BN 256
#define BKC 64
#define NC (KDIM / BKC)
#define OFF_AH 0
#define OFF_AL 16384
#define OFF_BH 32768
#define OFF_BL 65536
#define STAGE_BYTES 98304
#define GSMEM_TOTAL (2 * STAGE_BYTES)

__global__ __launch_bounds__(256, 1)
void gemm_bf16x3(const __nv_bfloat16* __restrict__ Ah, const __nv_bfloat16* __restrict__ Al,
                 const __nv_bfloat16* __restrict__ Bh, const __nv_bfloat16* __restrict__ Bl,
                 float* __restrict__ C, int ldC)
{
    extern __shared__ char smem[];
    const uint32_t sbase = smem_u32(smem);
    const int tid  = threadIdx.x;
    const int lane = tid & 31;
    const int wid  = tid >> 5;
    const int wm   = wid >> 2;
    const int wn   = wid & 3;
    const int m0 = blockIdx.y * BM;
    const int n0 = blockIdx.x * BN;

    const __nv_bfloat16* gA[2] = { Ah + (size_t)m0 * KDIM, Al + (size_t)m0 * KDIM };
    const __nv_bfloat16* gB[2] = { Bh + (size_t)n0 * KDIM, Bl + (size_t)n0 * KDIM };

    uint32_t aRow[4], aXor[4];
#pragma unroll
    for (int mt = 0; mt < 4; mt++) {
        uint32_t r = wm * 64 + mt * 16 + (lane & 15);
        aRow[mt] = r * 128;
        aXor[mt] = (aRow[mt] >> 3) & 0x70;
    }
    const uint32_t aKb = (lane >> 4);
    uint32_t bRow[4], bXor[4];
#pragma unroll
    for (int p = 0; p < 4; p++) {
        uint32_t r = wn * 64 + p * 16 + (lane & 7) + ((lane >> 4) << 3);
        bRow[p] = r * 128;
        bXor[p] = (bRow[p] >> 3) & 0x70;
    }
    const uint32_t bKb = ((lane >> 3) & 1);

    float acc[4][8][4];
#pragma unroll
    for (int i = 0; i < 4; i++)
#pragma unroll
        for (int j = 0; j < 8; j++)
#pragma unroll
            for (int q = 0; q < 4; q++) acc[i][j][q] = 0.0f;

    auto load_chunk = [&](int c, int st) {
        const uint32_t stg = sbase + st * STAGE_BYTES;
        const int koff = c * BKC;
#pragma unroll
        for (int p = 0; p < 4; p++) {
            int rem = p * 256 + tid;
            int r = rem >> 3, kb = rem & 7;
            cpasync16(stg + OFF_AH + swz128(r * 128 + kb * 16),
                      gA[0] + (size_t)r * KDIM + koff + kb * 8);
        }
#pragma unroll
        for (int p = 0; p < 4; p++) {
            int rem = p * 256 + tid;
            int r = rem >> 3, kb = rem & 7;
            cpasync16(stg + OFF_AL + swz128(r * 128 + kb * 16),
                      gA[1] + (size_t)r * KDIM + koff + kb * 8);
        }
#pragma unroll
        for (int p = 0; p < 8; p++) {
            int rem = p * 256 + tid;
            int r = rem >> 3, kb = rem & 7;
            cpasync16(stg + OFF_BH + swz128(r * 128 + kb * 16),
                      gB[0] + (size_t)r * KDIM + koff + kb * 8);
        }
#pragma unroll
        for (int p = 0; p < 8; p++) {
            int rem = p * 256 + tid;
            int r = rem >> 3, kb = rem & 7;
            cpasync16(stg + OFF_BL + swz128(r * 128 + kb * 16),
                      gB[1] + (size_t)r * KDIM + koff + kb * 8);
        }
    };

    load_chunk(0, 0);
    cp_commit();
    cp_wait0();
    __syncthreads();

    for (int ch = 0; ch < NC; ch++) {
        if (ch + 1 < NC) load_chunk(ch + 1, (ch + 1) & 1);
        cp_commit();

        const uint32_t stg = sbase + (ch & 1) * STAGE_BYTES;
#pragma unroll
        for (int q = 0; q < 4; q++) {
            const uint32_t kb_a = (q * 2 + aKb) * 16;
            const uint32_t kb_b = (q * 2 + bKb) * 16;
            uint32_t ah[4][4], al[4][4], bh[4][4], bl[4][4];
#pragma unroll
            for (int mt = 0; mt < 4; mt++) {
                uint32_t ad = stg + aRow[mt] + (kb_a ^ aXor[mt]);
                LDSM4(ah[mt], ad + OFF_AH);
                LDSM4(al[mt], ad + OFF_AL);
            }
#pragma unroll
            for (int p = 0; p < 4; p++) {
                uint32_t bd = stg + bRow[p] + (kb_b ^ bXor[p]);
                LDSM4(bh[p], bd + OFF_BH);
                LDSM4(bl[p], bd + OFF_BL);
            }
#pragma unroll
            for (int mt = 0; mt < 4; mt++) {
#pragma unroll
                for (int nt = 0; nt < 8; nt++) {
                    const int p = nt >> 1, bi = (nt & 1) * 2;
                    MMA16816(acc[mt][nt], ah[mt], bh[p][bi], bh[p][bi + 1]);
                    MMA16816(acc[mt][nt], ah[mt], bl[p][bi], bl[p][bi + 1]);
                    MMA16816(acc[mt][nt], al[mt], bh[p][bi], bh[p][bi + 1]);
                }
            }
        }
        cp_wait0();
        __syncthreads();
    }

    const int rw = m0 + wm * 64 + (lane >> 2);
    const int cw = n0 + wn * 64 + (lane & 3) * 2;
#pragma unroll
    for (int mt = 0; mt < 4; mt++) {
#pragma unroll
        for (int nt = 0; nt < 8; nt++) {
            float* p0 = C + (size_t)(rw + mt * 16) * ldC + cw + nt * 8;
            float* p1 = C + (size_t)(rw + mt * 16 + 8) * ldC + cw + nt * 8;
            *(float2*)p0 = make_float2(acc[mt][nt][0], acc[mt][nt][1]);
            *(float2*)p1 = make_float2(acc[mt][nt][2], acc[mt][nt][3]);
        }
    }
}

// ---------------- max reduction + int8 quantize -----------------------------
__global__ void reset_max_kernel() { g_maxbits[0] = 0; g_maxbits[1] = 0; }

__global__ __launch_bounds__(256)
void max_kernel(const float* __restrict__ in, int n4, int slot)
{
    float m = 0.0f;
    for (int i = blockIdx.x * blockDim.x + threadIdx.x; i < n4; i += gridDim.x * blockDim.x) {
        float4 v = ((const float4*)in)[i];
        m = fmaxf(m, fmaxf(fmaxf(fabsf(v.x), fabsf(v.y)), fmaxf(fabsf(v.z), fabsf(v.w))));
    }
#pragma unroll
    for (int o = 16; o > 0; o >>= 1)
        m = fmaxf(m, __shfl_xor_sync(0xffffffff, m, o));
    __shared__ float wmax[8];
    if ((threadIdx.x & 31) == 0) wmax[threadIdx.x >> 5] = m;
    __syncthreads();
    if (threadIdx.x < 8) {
        float t = wmax[threadIdx.x];
#pragma unroll
        for (int o = 4; o > 0; o >>= 1)
            t = fmaxf(t, __shfl_xor_sync(0xff, t, o));
        if (threadIdx.x == 0) atomicMax(&g_maxbits[slot], __float_as_uint(t));
    }
}

__global__ __launch_bounds__(256)
void quant_kernel(const float* __restrict__ in, int8_t* __restrict__ hi,
                  int8_t* __restrict__ lo, int n4, int slot)
{
    int i = blockIdx.x * blockDim.x + threadIdx.x;
    if (i >= n4) return;
    float mx = __uint_as_float(g_maxbits[slot]);
    if (mx == 0.f) mx = 1.f;
    float r = 16256.0f / mx;
    float4 v = ((const float4*)in)[i];
    int vi[4] = { __float2int_rn(v.x * r), __float2int_rn(v.y * r),
                  __float2int_rn(v.z * r), __float2int_rn(v.w * r) };
    char4 h, l;
    int h0 = (vi[0] + 64) >> 7; h.x = (char)h0; l.x = (char)(vi[0] - (h0 << 7));
    int h1 = (vi[1] + 64) >> 7; h.y = (char)h1; l.y = (char)(vi[1] - (h1 << 7));
    int h2 = (vi[2] + 64) >> 7; h.z = (char)h2; l.z = (char)(vi[2] - (h2 << 7));
    int h3 = (vi[3] + 64) >> 7; h.w = (char)h3; l.w = (char)(vi[3] - (h3 << 7));
    ((char4*)hi)[i] = h;
    ((char4*)lo)[i] = l;
}

// ---------------- bf16 split (for w_out) ------------------------------------
__global__ __launch_bounds__(256)
void split_kernel(const float* __restrict__ in, __nv_bfloat16* __restrict__ hi,
                  __nv_bfloat16* __restrict__ lo, int n4)
{
    int i = blockIdx.x * blockDim.x + threadIdx.x;
    if (i >= n4) return;
    float4 v = ((const float4*)in)[i];
    __nv_bfloat16 h0 = __float2bfloat16(v.x), h1 = __float2bfloat16(v.y);
    __nv_bfloat16 h2 = __float2bfloat16(v.z), h3 = __float2bfloat16(v.w);
    __nv_bfloat16 l0 = __float2bfloat16(v.x - __bfloat162float(h0));
    __nv_bfloat16 l1 = __float2bfloat16(v.y - __bfloat162float(h1));
    __nv_bfloat16 l2 = __float2bfloat16(v.z - __bfloat162float(h2));
    __nv_bfloat16 l3 = __float2bfloat16(v.w - __bfloat162float(h3));
    ((__nv_bfloat162*)hi)[i * 2 + 0] = __nv_bfloat162(h0, h1);
    ((__nv_bfloat162*)hi)[i * 2 + 1] = __nv_bfloat162(h2, h3);
    ((__nv_bfloat162*)lo)[i * 2 + 0] = __nv_bfloat162(l0, l1);
    ((__nv_bfloat162*)lo)[i * 2 + 1] = __nv_bfloat162(l2, l3);
}

// ---------------- gate + causal conv + BCx gate + states; y -> bf16 hi/lo ---
#define TPER 8
__device__ __forceinline__ float bx_at(int t, int d) {
    const float* p = &g_bcx[(size_t)t * BCX_COLS];
    return p[d] * p[2 * CONV_DIM + d];
}

__global__ __launch_bounds__(256)
void conv_gate_kernel(const float* __restrict__ cw, float* __restrict__ states_out)
{
    int d  = blockIdx.x * blockDim.x + threadIdx.x;
    int t0 = blockIdx.y * TPER;
    int pos0 = t0 & (SEQ_LEN - 1);

    float w0 = cw[d * KSZ + 0];
    float w1 = cw[d * KSZ + 1];
    float w2 = cw[d * KSZ + 2];
    float w3 = cw[d * KSZ + 3];

    float h0 = 0.f, h1 = 0.f, h2 = 0.f;
    if (pos0 >= 3) h0 = bx_at(t0 - 3, d);
    if (pos0 >= 2) h1 = bx_at(t0 - 2, d);
    if (pos0 >= 1) h2 = bx_at(t0 - 1, d);

#pragma unroll
    for (int i = 0; i < TPER; i++) {
        int t = t0 + i;
        float bx = bx_at(t, d);
        float conv = fmaf(w0, h0, fmaf(w1, h1, fmaf(w2, h2, w3 * bx)));
        float c = g_bcx[(size_t)t * BCX_COLS + CONV_DIM + d];
        float yv = c * conv;
        size_t yi = (size_t)t * CONV_DIM + d;
        __nv_bfloat16 yh = __float2bfloat16(yv);
        g_yh[yi] = yh;
        g_yl[yi] = __float2bfloat16(yv - __bfloat162float(yh));

        int pos = pos0 + i;
        if (pos >= SEQ_LEN - (KSZ - 1)) {
            int seq = t >> 12;
            int r   = pos - (SEQ_LEN - (KSZ - 1));
            states_out[((size_t)seq * (KSZ - 1) + r) * CONV_DIM + d] = bx;
        }
        h0 = h1; h1 = h2; h2 = bx;
    }
}

// ---------------- launch -----------------------------------------------------
extern "C" void kernel_launch(void* const* d_in, const int* in_sizes, int n_in,
                              void* d_out, int out_size)
{
    const float* hidden = (const float*)d_in[0];
    const float* w_in   = (const float*)d_in[1];
    const float* convw  = (const float*)d_in[2];
    const float* w_out  = (const float*)d_in[3];
    float* out = (float*)d_out;

    float* bcx; int8_t *qah, *qal, *qbh, *qbl;
    __nv_bfloat16 *wouth, *woutl, *yh, *yl;
    cudaGetSymbolAddress((void**)&bcx,   g_bcx);
    cudaGetSymbolAddress((void**)&qah,   g_qah);
    cudaGetSymbolAddress((void**)&qal,   g_qal);
    cudaGetSymbolAddress((void**)&qbh,   g_qbh);
    cudaGetSymbolAddress((void**)&qbl,   g_qbl);
    cudaGetSymbolAddress((void**)&wouth, g_wouth);
    cudaGetSymbolAddress((void**)&woutl, g_woutl);
    cudaGetSymbolAddress((void**)&yh,    g_yh);
    cudaGetSymbolAddress((void**)&yl,    g_yl);

    cudaFuncSetAttribute(gemm_s8x3,   cudaFuncAttributeMaxDynamicSharedMemorySize, IGSMEM);
    cudaFuncSetAttribute(gemm_bf16x3, cudaFuncAttributeMaxDynamicSharedMemorySize, GSMEM_TOTAL);

    // 0) max + quantize hidden / w_in ; split w_out
    reset_max_kernel<<<1, 1>>>();
    {
        int n4h = NTOK * KDIM / 4;
        int n4w = BCX_COLS * KDIM / 4;
        max_kernel<<<1024, 256>>>(hidden, n4h, 0);
        max_kernel<<<1024, 256>>>(w_in,   n4w, 1);
        quant_kernel<<<n4h / 256, 256>>>(hidden, qah, qal, n4h, 0);
        quant_kernel<<<n4w / 256, 256>>>(w_in,   qbh, qbl, n4w, 1);
        int n4o = HIDDEN * KDIM / 4;
        split_kernel<<<n4o / 256, 256>>>(w_out, wouth, woutl, n4o);
    }

    // 1) GEMM1 (int8x3): bcx = hidden @ w_in^T  [16384 x 6144]
    gemm_s8x3<<<dim3(BCX_COLS / 128, NTOK / 128), 256, IGSMEM>>>(qah, qal, qbh, qbl, bcx, BCX_COLS);

    // 2) conv + gates + states (+ y split)
    conv_gate_kernel<<<dim3(CONV_DIM / 256, NTOK / TPER), 256>>>(convw, out + (size_t)NTOK * HIDDEN);

    // 3) GEMM2 (bf16x3): out = y @ w_out^T  [16384 x 2048]
    gemm_bf16x3<<<dim3(HIDDEN / BN, NTOK / BM), 256, GSMEM_TOTAL>>>(yh, yl, wouth, woutl, out, HIDDEN);
}

// round 6
// speedup vs baseline: 2.7709x; 2.7709x over previous
#include <cuda_runtime.h>
#include <cuda_bf16.h>
#include <stdint.h>

#define NUM_SEQS 4
#define SEQ_LEN  4096
#define NTOK     16384
#define HIDDEN   2048
#define CONV_DIM 2048
#define KSZ      4
#define BCX_COLS 6144
#define KDIM     2048

// ---------------- scratch (static device globals; allocation-free) ----------
__device__ float g_bcx[(size_t)NTOK * BCX_COLS];
__device__ __nv_bfloat16 g_ah[(size_t)NTOK * KDIM];
__device__ __nv_bfloat16 g_al[(size_t)NTOK * KDIM];
__device__ __nv_bfloat16 g_winh[(size_t)BCX_COLS * KDIM];
__device__ __nv_bfloat16 g_winl[(size_t)BCX_COLS * KDIM];
__device__ __nv_bfloat16 g_wouth[(size_t)HIDDEN * KDIM];
__device__ __nv_bfloat16 g_woutl[(size_t)HIDDEN * KDIM];
__device__ __nv_bfloat16 g_yh[(size_t)NTOK * KDIM];
__device__ __nv_bfloat16 g_yl[(size_t)NTOK * KDIM];

// ---------------- ptx helpers (baseline ISA only) ----------------------------
__device__ __forceinline__ uint32_t smem_u32(const void* p) {
    uint32_t a;
    asm("{ .reg .u64 t; cvta.to.shared.u64 t, %1; cvt.u32.u64 %0, t; }" : "=r"(a) : "l"(p));
    return a;
}
__device__ __forceinline__ void cpasync16(uint32_t dst, const void* src) {
    asm volatile("cp.async.cg.shared.global [%0], [%1], 16;" :: "r"(dst), "l"(src));
}
__device__ __forceinline__ void cp_commit() { asm volatile("cp.async.commit_group;" ::: "memory"); }
__device__ __forceinline__ void cp_wait1()  { asm volatile("cp.async.wait_group 1;" ::: "memory"); }

#define LDSM4(r, addr)                                                      \
    asm volatile("ldmatrix.sync.aligned.m8n8.x4.shared.b16 {%0,%1,%2,%3}, [%4];" \
        : "=r"((r)[0]), "=r"((r)[1]), "=r"((r)[2]), "=r"((r)[3]) : "r"(addr))

#define MMA16816(acc, a, b0r, b1r)                                          \
    asm volatile("mma.sync.aligned.m16n8k16.row.col.f32.bf16.bf16.f32 "     \
        "{%0,%1,%2,%3}, {%4,%5,%6,%7}, {%8,%9}, {%0,%1,%2,%3};"             \
        : "+f"((acc)[0]), "+f"((acc)[1]), "+f"((acc)[2]), "+f"((acc)[3])    \
        : "r"((a)[0]), "r"((a)[1]), "r"((a)[2]), "r"((a)[3]),               \
          "r"(b0r), "r"(b1r))

// SW64 swizzle for 64B rows (validated pattern: XOR row bits [2:1] into slot bits)
__device__ __forceinline__ uint32_t swz64(uint32_t off) { return off ^ ((off >> 3) & 0x30); }

// ---------------- bf16x3 GEMM: C[M,N] = (Ah+Al)[M,K] @ (Bh+Bl)[N,K]^T -------
// CTA 128x128, 4 warps (2x2), warp tile 64x64, BK=32, 3-stage, 2 CTAs/SM
#define BM 128
#define BN 128
#define BKC 32
#define NC (KDIM / BKC)              // 64
// stage layout (64B rows): Ah 8K | Al 8K | Bh 8K | Bl 8K = 32KB
#define OFF_AH 0
#define OFF_AL 8192
#define OFF_BH 16384
#define OFF_BL 24576
#define STAGE_BYTES 32768
#define NSTAGE 3
#define GSMEM_TOTAL (NSTAGE * STAGE_BYTES)   // 96KB

__global__ __launch_bounds__(128, 2)
void gemm_bf16x3(const __nv_bfloat16* __restrict__ Ah, const __nv_bfloat16* __restrict__ Al,
                 const __nv_bfloat16* __restrict__ Bh, const __nv_bfloat16* __restrict__ Bl,
                 float* __restrict__ C, int ldC)
{
    extern __shared__ char smem[];
    const uint32_t sbase = smem_u32(smem);
    const int tid  = threadIdx.x;
    const int lane = tid & 31;
    const int wid  = tid >> 5;
    const int wm   = wid >> 1;       // 0..1 (64 rows each)
    const int wn   = wid & 1;        // 0..1 (64 cols each)
    const int m0 = blockIdx.y * BM;
    const int n0 = blockIdx.x * BN;

    const __nv_bfloat16* gp[4] = { Ah + (size_t)m0 * KDIM, Al + (size_t)m0 * KDIM,
                                   Bh + (size_t)n0 * KDIM, Bl + (size_t)n0 * KDIM };

    // ldmatrix lane address components (64B rows)
    uint32_t aRow[4], aXor[4];
#pragma unroll
    for (int mt = 0; mt < 4; mt++) {
        uint32_t r = wm * 64 + mt * 16 + (lane & 15);
        aRow[mt] = r * 64;
        aXor[mt] = (aRow[mt] >> 3) & 0x30;
    }
    const uint32_t aS = (lane >> 4);             // + q*2
    uint32_t bRow[4], bXor[4];
#pragma unroll
    for (int p = 0; p < 4; p++) {
        uint32_t r = wn * 64 + p * 16 + (lane & 7) + ((lane >> 4) << 3);
        bRow[p] = r * 64;
        bXor[p] = (bRow[p] >> 3) & 0x30;
    }
    const uint32_t bS = ((lane >> 3) & 1);       // + q*2

    float acc[4][8][4];
#pragma unroll
    for (int i = 0; i < 4; i++)
#pragma unroll
        for (int j = 0; j < 8; j++)
#pragma unroll
            for (int q = 0; q < 4; q++) acc[i][j][q] = 0.0f;

    // stage filler: 4 planes x 512 16B-units, 128 threads -> 16 cp.async/thread
    auto load_chunk = [&](int c, int st) {
        const uint32_t stg = sbase + st * STAGE_BYTES;
        const int koff = c * BKC;
#pragma unroll
        for (int m = 0; m < 4; m++) {
            const uint32_t ob = stg + m * 8192;
#pragma unroll
            for (int p = 0; p < 4; p++) {
                int u = p * 128 + tid;           // 0..511
                int r = u >> 2, s = u & 3;
                cpasync16(ob + swz64((uint32_t)(r * 64 + s * 16)),
                          gp[m] + (size_t)r * KDIM + koff + s * 8);
            }
        }
    };

    // prologue: stages 0,1
    load_chunk(0, 0); cp_commit();
    load_chunk(1, 1); cp_commit();
    cp_wait1();
    __syncthreads();

    for (int ch = 0; ch < NC; ch++) {
        if (ch + 2 < NC) load_chunk(ch + 2, (ch + 2) % 3);
        cp_commit();

        const uint32_t stg = sbase + (ch % 3) * STAGE_BYTES;
#pragma unroll
        for (int q = 0; q < 2; q++) {
            const uint32_t s_a = (q * 2 + aS) * 16;
            const uint32_t s_b = (q * 2 + bS) * 16;
            uint32_t ah[4][4], al[4][4], bh[4][4], bl[4][4];
#pragma unroll
            for (int mt = 0; mt < 4; mt++) {
                uint32_t ad = stg + aRow[mt] + (s_a ^ aXor[mt]);
                LDSM4(ah[mt], ad + OFF_AH);
                LDSM4(al[mt], ad + OFF_AL);
            }
#pragma unroll
            for (int p = 0; p < 4; p++) {
                uint32_t bd = stg + bRow[p] + (s_b ^ bXor[p]);
                LDSM4(bh[p], bd + OFF_BH);
                LDSM4(bl[p], bd + OFF_BL);
            }
#pragma unroll
            for (int mt = 0; mt < 4; mt++) {
#pragma unroll
                for (int nt = 0; nt < 8; nt++) {
                    const int p = nt >> 1, bi = (nt & 1) * 2;
                    MMA16816(acc[mt][nt], ah[mt], bh[p][bi], bh[p][bi + 1]);
                    MMA16816(acc[mt][nt], ah[mt], bl[p][bi], bl[p][bi + 1]);
                    MMA16816(acc[mt][nt], al[mt], bh[p][bi], bh[p][bi + 1]);
                }
            }
        }
        cp_wait1();
        __syncthreads();
    }

    // epilogue
    const int rw = m0 + wm * 64 + (lane >> 2);
    const int cw = n0 + wn * 64 + (lane & 3) * 2;
#pragma unroll
    for (int mt = 0; mt < 4; mt++) {
#pragma unroll
        for (int nt = 0; nt < 8; nt++) {
            float* p0 = C + (size_t)(rw + mt * 16) * ldC + cw + nt * 8;
            float* p1 = C + (size_t)(rw + mt * 16 + 8) * ldC + cw + nt * 8;
            *(float2*)p0 = make_float2(acc[mt][nt][0], acc[mt][nt][1]);
            *(float2*)p1 = make_float2(acc[mt][nt][2], acc[mt][nt][3]);
        }
    }
}

// ---------------- fp32 -> bf16 hi/lo split ----------------------------------
__global__ __launch_bounds__(256)
void split_kernel(const float* __restrict__ in, __nv_bfloat16* __restrict__ hi,
                  __nv_bfloat16* __restrict__ lo, int n4)
{
    int i = blockIdx.x * blockDim.x + threadIdx.x;
    if (i >= n4) return;
    float4 v = ((const float4*)in)[i];
    __nv_bfloat16 h0 = __float2bfloat16(v.x), h1 = __float2bfloat16(v.y);
    __nv_bfloat16 h2 = __float2bfloat16(v.z), h3 = __float2bfloat16(v.w);
    __nv_bfloat16 l0 = __float2bfloat16(v.x - __bfloat162float(h0));
    __nv_bfloat16 l1 = __float2bfloat16(v.y - __bfloat162float(h1));
    __nv_bfloat16 l2 = __float2bfloat16(v.z - __bfloat162float(h2));
    __nv_bfloat16 l3 = __float2bfloat16(v.w - __bfloat162float(h3));
    ((__nv_bfloat162*)hi)[i * 2 + 0] = __nv_bfloat162(h0, h1);
    ((__nv_bfloat162*)hi)[i * 2 + 1] = __nv_bfloat162(h2, h3);
    ((__nv_bfloat162*)lo)[i * 2 + 0] = __nv_bfloat162(l0, l1);
    ((__nv_bfloat162*)lo)[i * 2 + 1] = __nv_bfloat162(l2, l3);
}

// ---------------- gate + causal conv + BCx gate + states; y -> bf16 hi/lo ---
#define TPER 8
__device__ __forceinline__ float bx_at(int t, int d) {
    const float* p = &g_bcx[(size_t)t * BCX_COLS];
    return p[d] * p[2 * CONV_DIM + d];
}

__global__ __launch_bounds__(256)
void conv_gate_kernel(const float* __restrict__ cw, float* __restrict__ states_out)
{
    int d  = blockIdx.x * blockDim.x + threadIdx.x;
    int t0 = blockIdx.y * TPER;
    int pos0 = t0 & (SEQ_LEN - 1);

    float w0 = cw[d * KSZ + 0];
    float w1 = cw[d * KSZ + 1];
    float w2 = cw[d * KSZ + 2];
    float w3 = cw[d * KSZ + 3];

    float h0 = 0.f, h1 = 0.f, h2 = 0.f;
    if (pos0 >= 3) h0 = bx_at(t0 - 3, d);
    if (pos0 >= 2) h1 = bx_at(t0 - 2, d);
    if (pos0 >= 1) h2 = bx_at(t0 - 1, d);

#pragma unroll
    for (int i = 0; i < TPER; i++) {
        int t = t0 + i;
        float bx = bx_at(t, d);
        float conv = fmaf(w0, h0, fmaf(w1, h1, fmaf(w2, h2, w3 * bx)));
        float c = g_bcx[(size_t)t * BCX_COLS + CONV_DIM + d];
        float yv = c * conv;
        size_t yi = (size_t)t * CONV_DIM + d;
        __nv_bfloat16 yh = __float2bfloat16(yv);
        g_yh[yi] = yh;
        g_yl[yi] = __float2bfloat16(yv - __bfloat162float(yh));

        int pos = pos0 + i;
        if (pos >= SEQ_LEN - (KSZ - 1)) {
            int seq = t >> 12;
            int r   = pos - (SEQ_LEN - (KSZ - 1));
            states_out[((size_t)seq * (KSZ - 1) + r) * CONV_DIM + d] = bx;
        }
        h0 = h1; h1 = h2; h2 = bx;
    }
}

// ---------------- launch -----------------------------------------------------
extern "C" void kernel_launch(void* const* d_in, const int* in_sizes, int n_in,
                              void* d_out, int out_size)
{
    const float* hidden = (const float*)d_in[0];
    const float* w_in   = (const float*)d_in[1];
    const float* convw  = (const float*)d_in[2];
    const float* w_out  = (const float*)d_in[3];
    float* out = (float*)d_out;

    float* bcx; __nv_bfloat16 *ah, *al, *winh, *winl, *wouth, *woutl, *yh, *yl;
    cudaGetSymbolAddress((void**)&bcx,   g_bcx);
    cudaGetSymbolAddress((void**)&ah,    g_ah);
    cudaGetSymbolAddress((void**)&al,    g_al);
    cudaGetSymbolAddress((void**)&winh,  g_winh);
    cudaGetSymbolAddress((void**)&winl,  g_winl);
    cudaGetSymbolAddress((void**)&wouth, g_wouth);
    cudaGetSymbolAddress((void**)&woutl, g_woutl);
    cudaGetSymbolAddress((void**)&yh,    g_yh);
    cudaGetSymbolAddress((void**)&yl,    g_yl);

    cudaFuncSetAttribute(gemm_bf16x3, cudaFuncAttributeMaxDynamicSharedMemorySize, GSMEM_TOTAL);

    // splits
    {
        int n4 = NTOK * KDIM / 4;
        split_kernel<<<n4 / 256, 256>>>(hidden, ah, al, n4);
        n4 = BCX_COLS * KDIM / 4;
        split_kernel<<<n4 / 256, 256>>>(w_in, winh, winl, n4);
        n4 = HIDDEN * KDIM / 4;
        split_kernel<<<n4 / 256, 256>>>(w_out, wouth, woutl, n4);
    }

    // GEMM1: bcx = hidden @ w_in^T  [16384 x 6144]
    gemm_bf16x3<<<dim3(BCX_COLS / BN, NTOK / BM), 128, GSMEM_TOTAL>>>(ah, al, winh, winl, bcx, BCX_COLS);

    // conv + gates + states (+ y split)
    conv_gate_kernel<<<dim3(CONV_DIM / 256, NTOK / TPER), 256>>>(convw, out + (size_t)NTOK * HIDDEN);

    // GEMM2: out = y @ w_out^T  [16384 x 2048]
    gemm_bf16x3<<<dim3(HIDDEN / BN, NTOK / BM), 128, GSMEM_TOTAL>>>(yh, yl, wouth, woutl, out, HIDDEN);
}

// round 7
// speedup vs baseline: 4.1834x; 1.5098x over previous
#include <cuda_runtime.h>
#include <cuda_bf16.h>
#include <stdint.h>

#define NUM_SEQS 4
#define SEQ_LEN  4096
#define NTOK     16384
#define HIDDEN   2048
#define CONV_DIM 2048
#define KSZ      4
#define BCX_COLS 6144
#define KDIM     2048

// ---------------- scratch (static device globals; allocation-free) ----------
__device__ float g_bcx[(size_t)NTOK * BCX_COLS];     // 402 MB
__device__ float g_a32[(size_t)NTOK * KDIM];         // rounded hidden
__device__ float g_w1r[(size_t)BCX_COLS * KDIM];     // rounded w_in
__device__ float g_w2r[(size_t)HIDDEN * KDIM];       // rounded w_out
__device__ float g_y[(size_t)NTOK * KDIM];           // rounded y

// ---------------- ptx helpers (baseline ISA only) ----------------------------
__device__ __forceinline__ uint32_t smem_u32(const void* p) {
    uint32_t a;
    asm("{ .reg .u64 t; cvta.to.shared.u64 t, %1; cvt.u32.u64 %0, t; }" : "=r"(a) : "l"(p));
    return a;
}
__device__ __forceinline__ void cpasync16(uint32_t dst, const void* src) {
    asm volatile("cp.async.cg.shared.global [%0], [%1], 16;" :: "r"(dst), "l"(src));
}
__device__ __forceinline__ void cp_commit() { asm volatile("cp.async.commit_group;" ::: "memory"); }
__device__ __forceinline__ void cp_wait1()  { asm volatile("cp.async.wait_group 1;" ::: "memory"); }

__device__ __forceinline__ float tf32r(float x) {
    float y; asm("cvt.rna.tf32.f32 %0, %1;" : "=f"(y) : "f"(x)); return y;
}

#define LDSM4(r, addr)                                                      \
    asm volatile("ldmatrix.sync.aligned.m8n8.x4.shared.b16 {%0,%1,%2,%3}, [%4];" \
        : "=r"((r)[0]), "=r"((r)[1]), "=r"((r)[2]), "=r"((r)[3]) : "r"(addr))

#define MMATF32(acc, a, b0r, b1r)                                           \
    asm volatile("mma.sync.aligned.m16n8k8.row.col.f32.tf32.tf32.f32 "      \
        "{%0,%1,%2,%3}, {%4,%5,%6,%7}, {%8,%9}, {%0,%1,%2,%3};"             \
        : "+f"((acc)[0]), "+f"((acc)[1]), "+f"((acc)[2]), "+f"((acc)[3])    \
        : "r"((a)[0]), "r"((a)[1]), "r"((a)[2]), "r"((a)[3]),               \
          "r"(b0r), "r"(b1r))

__device__ __forceinline__ uint32_t swz128(uint32_t off) { return off ^ ((off >> 3) & 0x70); }

// ---------------- tf32 GEMM: C[M,N] = A[M,K] @ B[N,K]^T ---------------------
// CTA 128x128, 4 warps (2x2), warp tile 64x64, BK=32 floats (128B rows),
// 3-stage cp.async pipeline, 2 CTAs/SM.
#define BM 128
#define BN 128
#define BKF 32
#define NC (KDIM / BKF)              // 64
#define OFF_A 0
#define OFF_B 16384
#define STAGE_BYTES 32768
#define GSMEM_TOTAL (3 * STAGE_BYTES)   // 96KB

__global__ __launch_bounds__(128, 2)
void gemm_tf32(const float* __restrict__ A, const float* __restrict__ B,
               float* __restrict__ C, int ldC)
{
    extern __shared__ char smem[];
    const uint32_t sbase = smem_u32(smem);
    const int tid  = threadIdx.x;
    const int lane = tid & 31;
    const int wid  = tid >> 5;
    const int wm   = wid >> 1;       // 0..1 (64 rows)
    const int wn   = wid & 1;        // 0..1 (64 cols)
    const int m0 = blockIdx.y * BM;
    const int n0 = blockIdx.x * BN;

    const float* gA = A + (size_t)m0 * KDIM;
    const float* gB = B + (size_t)n0 * KDIM;

    // ldmatrix lane address components
    // A: x4 = [m0-7/kq0, m8-15/kq0, m0-7/kq1, m8-15/kq1] for k8 step s (kq pair 2s,2s+1)
    const uint32_t aRowLoc = (lane & 7) + ((lane >> 3) & 1) * 8;
    const uint32_t aKqSel  = (lane >> 4);          // 0/1
    uint32_t aBase[4], aXor[4];
#pragma unroll
    for (int mt = 0; mt < 4; mt++) {
        uint32_t r = wm * 64 + mt * 16 + aRowLoc;
        aBase[mt] = r * 128;
        aXor[mt] = (aBase[mt] >> 3) & 0x70;
    }
    // B: x4 = [n0-7/kq0, n0-7/kq1, n8-15/kq0, n8-15/kq1]
    const uint32_t bRowLoc = (lane & 7) + (lane >> 4) * 8;
    const uint32_t bKqSel  = (lane >> 3) & 1;
    uint32_t bBase[4], bXor[4];
#pragma unroll
    for (int nt = 0; nt < 4; nt++) {
        uint32_t r = wn * 64 + nt * 16 + bRowLoc;
        bBase[nt] = r * 128;
        bXor[nt] = (bBase[nt] >> 3) & 0x70;
    }

    float acc[4][8][4];
#pragma unroll
    for (int i = 0; i < 4; i++)
#pragma unroll
        for (int j = 0; j < 8; j++)
#pragma unroll
            for (int q = 0; q < 4; q++) acc[i][j][q] = 0.0f;

    // stage filler: A,B each 1024 16B-units; 128 threads -> 8+8 cp.async/thread
    auto load_chunk = [&](int c, int st) {
        const uint32_t stg = sbase + st * STAGE_BYTES;
        const int koff = c * BKF;
#pragma unroll
        for (int p = 0; p < 8; p++) {
            int u = p * 128 + tid;
            int r = u >> 3, kq = u & 7;
            cpasync16(stg + OFF_A + swz128(r * 128 + kq * 16),
                      gA + (size_t)r * KDIM + koff + kq * 4);
        }
#pragma unroll
        for (int p = 0; p < 8; p++) {
            int u = p * 128 + tid;
            int r = u >> 3, kq = u & 7;
            cpasync16(stg + OFF_B + swz128(r * 128 + kq * 16),
                      gB + (size_t)r * KDIM + koff + kq * 4);
        }
    };

    load_chunk(0, 0); cp_commit();
    load_chunk(1, 1); cp_commit();
    cp_wait1();
    __syncthreads();

    for (int ch = 0; ch < NC; ch++) {
        if (ch + 2 < NC) load_chunk(ch + 2, (ch + 2) % 3);
        cp_commit();

        const uint32_t stg = sbase + (ch % 3) * STAGE_BYTES;
#pragma unroll
        for (int s = 0; s < 4; s++) {            // 4 k8-steps per 32-float chunk
            uint32_t af[4][4], bf[4][4];
#pragma unroll
            for (int mt = 0; mt < 4; mt++) {
                uint32_t slot = ((2 * s + aKqSel) * 16) ^ aXor[mt];
                LDSM4(af[mt], stg + OFF_A + aBase[mt] + slot);
            }
#pragma unroll
            for (int nt = 0; nt < 4; nt++) {
                uint32_t slot = ((2 * s + bKqSel) * 16) ^ bXor[nt];
                LDSM4(bf[nt], stg + OFF_B + bBase[nt] + slot);
            }
#pragma unroll
            for (int mt = 0; mt < 4; mt++) {
#pragma unroll
                for (int nt = 0; nt < 4; nt++) {
                    MMATF32(acc[mt][nt * 2 + 0], af[mt], bf[nt][0], bf[nt][1]);
                    MMATF32(acc[mt][nt * 2 + 1], af[mt], bf[nt][2], bf[nt][3]);
                }
            }
        }
        cp_wait1();
        __syncthreads();
    }

    // epilogue
    const int rw = m0 + wm * 64 + (lane >> 2);
    const int cw = n0 + wn * 64 + (lane & 3) * 2;
#pragma unroll
    for (int mt = 0; mt < 4; mt++) {
#pragma unroll
        for (int nt = 0; nt < 8; nt++) {
            float* p0 = C + (size_t)(rw + mt * 16) * ldC + cw + nt * 8;
            float* p1 = C + (size_t)(rw + mt * 16 + 8) * ldC + cw + nt * 8;
            *(float2*)p0 = make_float2(acc[mt][nt][0], acc[mt][nt][1]);
            *(float2*)p1 = make_float2(acc[mt][nt][2], acc[mt][nt][3]);
        }
    }
}

// ---------------- tf32 rounding copy ----------------------------------------
__global__ __launch_bounds__(256)
void round_kernel(const float* __restrict__ in, float* __restrict__ out, int n4)
{
    int i = blockIdx.x * blockDim.x + threadIdx.x;
    if (i >= n4) return;
    float4 v = ((const float4*)in)[i];
    v.x = tf32r(v.x); v.y = tf32r(v.y); v.z = tf32r(v.z); v.w = tf32r(v.w);
    ((float4*)out)[i] = v;
}

// ---------------- gate + causal conv + BCx gate + states --------------------
#define TPER 8
__device__ __forceinline__ float bx_at(int t, int d) {
    const float* p = &g_bcx[(size_t)t * BCX_COLS];
    return p[d] * p[2 * CONV_DIM + d];
}

__global__ __launch_bounds__(256)
void conv_gate_kernel(const float* __restrict__ cw, float* __restrict__ states_out)
{
    int d  = blockIdx.x * blockDim.x + threadIdx.x;
    int t0 = blockIdx.y * TPER;
    int pos0 = t0 & (SEQ_LEN - 1);

    float w0 = cw[d * KSZ + 0];
    float w1 = cw[d * KSZ + 1];
    float w2 = cw[d * KSZ + 2];
    float w3 = cw[d * KSZ + 3];

    float h0 = 0.f, h1 = 0.f, h2 = 0.f;
    if (pos0 >= 3) h0 = bx_at(t0 - 3, d);
    if (pos0 >= 2) h1 = bx_at(t0 - 2, d);
    if (pos0 >= 1) h2 = bx_at(t0 - 1, d);

#pragma unroll
    for (int i = 0; i < TPER; i++) {
        int t = t0 + i;
        float bx = bx_at(t, d);
        float conv = fmaf(w0, h0, fmaf(w1, h1, fmaf(w2, h2, w3 * bx)));
        float c = g_bcx[(size_t)t * BCX_COLS + CONV_DIM + d];
        g_y[(size_t)t * CONV_DIM + d] = tf32r(c * conv);

        int pos = pos0 + i;
        if (pos >= SEQ_LEN - (KSZ - 1)) {
            int seq = t >> 12;
            int r   = pos - (SEQ_LEN - (KSZ - 1));
            states_out[((size_t)seq * (KSZ - 1) + r) * CONV_DIM + d] = bx;
        }
        h0 = h1; h1 = h2; h2 = bx;
    }
}

// ---------------- launch -----------------------------------------------------
extern "C" void kernel_launch(void* const* d_in, const int* in_sizes, int n_in,
                              void* d_out, int out_size)
{
    const float* hidden = (const float*)d_in[0];
    const float* w_in   = (const float*)d_in[1];
    const float* convw  = (const float*)d_in[2];
    const float* w_out  = (const float*)d_in[3];
    float* out = (float*)d_out;

    float *bcx, *a32, *w1r, *w2r, *y;
    cudaGetSymbolAddress((void**)&bcx, g_bcx);
    cudaGetSymbolAddress((void**)&a32, g_a32);
    cudaGetSymbolAddress((void**)&w1r, g_w1r);
    cudaGetSymbolAddress((void**)&w2r, g_w2r);
    cudaGetSymbolAddress((void**)&y,   g_y);

    cudaFuncSetAttribute(gemm_tf32, cudaFuncAttributeMaxDynamicSharedMemorySize, GSMEM_TOTAL);

    // 0) tf32 rounding copies
    {
        int n4 = NTOK * KDIM / 4;
        round_kernel<<<n4 / 256, 256>>>(hidden, a32, n4);
        n4 = BCX_COLS * KDIM / 4;
        round_kernel<<<n4 / 256, 256>>>(w_in, w1r, n4);
        n4 = HIDDEN * KDIM / 4;
        round_kernel<<<n4 / 256, 256>>>(w_out, w2r, n4);
    }

    // 1) GEMM1: bcx = hidden @ w_in^T  [16384 x 6144]
    gemm_tf32<<<dim3(BCX_COLS / BN, NTOK / BM), 128, GSMEM_TOTAL>>>(a32, w1r, bcx, BCX_COLS);

    // 2) conv + gates + states (+ tf32-rounded y)
    conv_gate_kernel<<<dim3(CONV_DIM / 256, NTOK / TPER), 256>>>(convw, out + (size_t)NTOK * HIDDEN);

    // 3) GEMM2: out = y @ w_out^T  [16384 x 2048]
    gemm_tf32<<<dim3(HIDDEN / BN, NTOK / BM), 128, GSMEM_TOTAL>>>(y, w2r, out, HIDDEN);
}

// round 8
// speedup vs baseline: 7.5176x; 1.7970x over previous
#include <cuda_runtime.h>
#include <cuda_fp16.h>
#include <stdint.h>

#define NUM_SEQS 4
#define SEQ_LEN  4096
#define NTOK     16384
#define HIDDEN   2048
#define CONV_DIM 2048
#define KSZ      4
#define BCX_COLS 6144
#define KDIM     2048

// ---------------- scratch (static device globals; allocation-free) ----------
__device__ float g_bcx[(size_t)NTOK * BCX_COLS];     // 402 MB
__device__ __half g_ha[(size_t)NTOK * KDIM];         // fp16 hidden
__device__ __half g_w1[(size_t)BCX_COLS * KDIM];     // fp16 w_in
__device__ __half g_w2[(size_t)HIDDEN * KDIM];       // fp16 w_out
__device__ __half g_y[(size_t)NTOK * KDIM];          // fp16 y

// ---------------- ptx helpers (baseline ISA only) ----------------------------
__device__ __forceinline__ uint32_t smem_u32(const void* p) {
    uint32_t a;
    asm("{ .reg .u64 t; cvta.to.shared.u64 t, %1; cvt.u32.u64 %0, t; }" : "=r"(a) : "l"(p));
    return a;
}
__device__ __forceinline__ void cpasync16(uint32_t dst, const void* src) {
    asm volatile("cp.async.cg.shared.global [%0], [%1], 16;" :: "r"(dst), "l"(src));
}
__device__ __forceinline__ void cp_commit() { asm volatile("cp.async.commit_group;" ::: "memory"); }
__device__ __forceinline__ void cp_wait1()  { asm volatile("cp.async.wait_group 1;" ::: "memory"); }

#define LDSM4(r, addr)                                                      \
    asm volatile("ldmatrix.sync.aligned.m8n8.x4.shared.b16 {%0,%1,%2,%3}, [%4];" \
        : "=r"((r)[0]), "=r"((r)[1]), "=r"((r)[2]), "=r"((r)[3]) : "r"(addr))

#define MMAF16(acc, a, b0r, b1r)                                            \
    asm volatile("mma.sync.aligned.m16n8k16.row.col.f32.f16.f16.f32 "       \
        "{%0,%1,%2,%3}, {%4,%5,%6,%7}, {%8,%9}, {%0,%1,%2,%3};"             \
        : "+f"((acc)[0]), "+f"((acc)[1]), "+f"((acc)[2]), "+f"((acc)[3])    \
        : "r"((a)[0]), "r"((a)[1]), "r"((a)[2]), "r"((a)[3]),               \
          "r"(b0r), "r"(b1r))

// SW64 swizzle for 64B rows (validated in R6)
__device__ __forceinline__ uint32_t swz64(uint32_t off) { return off ^ ((off >> 3) & 0x30); }

// ---------------- fp16 GEMM: C[M,N] = A[M,K] @ B[N,K]^T ---------------------
// CTA 128x128, 4 warps (2x2), warp tile 64x64, BK=32 halves (64B rows),
// 3-stage cp.async pipeline, 2 CTAs/SM.
#define BM 128
#define BN 128
#define BKC 32
#define NC (KDIM / BKC)              // 64
#define OFF_A 0
#define OFF_B 8192
#define STAGE_BYTES 16384
#define GSMEM_TOTAL (3 * STAGE_BYTES)   // 48KB

__global__ __launch_bounds__(128, 2)
void gemm_f16(const __half* __restrict__ A, const __half* __restrict__ B,
              float* __restrict__ C, int ldC)
{
    extern __shared__ char smem[];
    const uint32_t sbase = smem_u32(smem);
    const int tid  = threadIdx.x;
    const int lane = tid & 31;
    const int wid  = tid >> 5;
    const int wm   = wid >> 1;       // 0..1 (64 rows)
    const int wn   = wid & 1;        // 0..1 (64 cols)
    const int m0 = blockIdx.y * BM;
    const int n0 = blockIdx.x * BN;

    const __half* gA = A + (size_t)m0 * KDIM;
    const __half* gB = B + (size_t)n0 * KDIM;

    // ldmatrix lane address components (64B rows)
    uint32_t aRow[4], aXor[4];
#pragma unroll
    for (int mt = 0; mt < 4; mt++) {
        uint32_t r = wm * 64 + mt * 16 + (lane & 15);
        aRow[mt] = r * 64;
        aXor[mt] = (aRow[mt] >> 3) & 0x30;
    }
    const uint32_t aS = (lane >> 4);             // + q*2
    uint32_t bRow[4], bXor[4];
#pragma unroll
    for (int p = 0; p < 4; p++) {
        uint32_t r = wn * 64 + p * 16 + (lane & 7) + ((lane >> 4) << 3);
        bRow[p] = r * 64;
        bXor[p] = (bRow[p] >> 3) & 0x30;
    }
    const uint32_t bS = ((lane >> 3) & 1);       // + q*2

    float acc[4][8][4];
#pragma unroll
    for (int i = 0; i < 4; i++)
#pragma unroll
        for (int j = 0; j < 8; j++)
#pragma unroll
            for (int q = 0; q < 4; q++) acc[i][j][q] = 0.0f;

    // stage filler: A,B each 512 16B-units; 128 threads -> 4+4 cp.async/thread
    auto load_chunk = [&](int c, int st) {
        const uint32_t stg = sbase + st * STAGE_BYTES;
        const int koff = c * BKC;
#pragma unroll
        for (int p = 0; p < 4; p++) {
            int u = p * 128 + tid;
            int r = u >> 2, s = u & 3;
            cpasync16(stg + OFF_A + swz64((uint32_t)(r * 64 + s * 16)),
                      gA + (size_t)r * KDIM + koff + s * 8);
        }
#pragma unroll
        for (int p = 0; p < 4; p++) {
            int u = p * 128 + tid;
            int r = u >> 2, s = u & 3;
            cpasync16(stg + OFF_B + swz64((uint32_t)(r * 64 + s * 16)),
                      gB + (size_t)r * KDIM + koff + s * 8);
        }
    };

    load_chunk(0, 0); cp_commit();
    load_chunk(1, 1); cp_commit();
    cp_wait1();
    __syncthreads();

    for (int ch = 0; ch < NC; ch++) {
        if (ch + 2 < NC) load_chunk(ch + 2, (ch + 2) % 3);
        cp_commit();

        const uint32_t stg = sbase + (ch % 3) * STAGE_BYTES;
#pragma unroll
        for (int q = 0; q < 2; q++) {            // 2 k16-steps per 32-half chunk
            const uint32_t s_a = (q * 2 + aS) * 16;
            const uint32_t s_b = (q * 2 + bS) * 16;
            uint32_t af[4][4], bf[4][4];
#pragma unroll
            for (int mt = 0; mt < 4; mt++)
                LDSM4(af[mt], stg + OFF_A + aRow[mt] + (s_a ^ aXor[mt]));
#pragma unroll
            for (int p = 0; p < 4; p++)
                LDSM4(bf[p], stg + OFF_B + bRow[p] + (s_b ^ bXor[p]));
#pragma unroll
            for (int mt = 0; mt < 4; mt++) {
#pragma unroll
                for (int nt = 0; nt < 8; nt++) {
                    const int p = nt >> 1, bi = (nt & 1) * 2;
                    MMAF16(acc[mt][nt], af[mt], bf[p][bi], bf[p][bi + 1]);
                }
            }
        }
        cp_wait1();
        __syncthreads();
    }

    // epilogue
    const int rw = m0 + wm * 64 + (lane >> 2);
    const int cw = n0 + wn * 64 + (lane & 3) * 2;
#pragma unroll
    for (int mt = 0; mt < 4; mt++) {
#pragma unroll
        for (int nt = 0; nt < 8; nt++) {
            float* p0 = C + (size_t)(rw + mt * 16) * ldC + cw + nt * 8;
            float* p1 = C + (size_t)(rw + mt * 16 + 8) * ldC + cw + nt * 8;
            *(float2*)p0 = make_float2(acc[mt][nt][0], acc[mt][nt][1]);
            *(float2*)p1 = make_float2(acc[mt][nt][2], acc[mt][nt][3]);
        }
    }
}

// ---------------- fp32 -> fp16 convert --------------------------------------
__global__ __launch_bounds__(256)
void cvt_f16_kernel(const float* __restrict__ in, __half* __restrict__ out, int n4)
{
    int i = blockIdx.x * blockDim.x + threadIdx.x;
    if (i >= n4) return;
    float4 v = ((const float4*)in)[i];
    ((__half2*)out)[i * 2 + 0] = __floats2half2_rn(v.x, v.y);
    ((__half2*)out)[i * 2 + 1] = __floats2half2_rn(v.z, v.w);
}

// ---------------- gate + causal conv + BCx gate + states; y -> fp16 ---------
#define TPER 8
__device__ __forceinline__ float bx_at(int t, int d) {
    const float* p = &g_bcx[(size_t)t * BCX_COLS];
    return p[d] * p[2 * CONV_DIM + d];
}

__global__ __launch_bounds__(256)
void conv_gate_kernel(const float* __restrict__ cw, float* __restrict__ states_out)
{
    int d  = blockIdx.x * blockDim.x + threadIdx.x;
    int t0 = blockIdx.y * TPER;
    int pos0 = t0 & (SEQ_LEN - 1);

    float w0 = cw[d * KSZ + 0];
    float w1 = cw[d * KSZ + 1];
    float w2 = cw[d * KSZ + 2];
    float w3 = cw[d * KSZ + 3];

    float h0 = 0.f, h1 = 0.f, h2 = 0.f;
    if (pos0 >= 3) h0 = bx_at(t0 - 3, d);
    if (pos0 >= 2) h1 = bx_at(t0 - 2, d);
    if (pos0 >= 1) h2 = bx_at(t0 - 1, d);

#pragma unroll
    for (int i = 0; i < TPER; i++) {
        int t = t0 + i;
        float bx = bx_at(t, d);
        float conv = fmaf(w0, h0, fmaf(w1, h1, fmaf(w2, h2, w3 * bx)));
        float c = g_bcx[(size_t)t * BCX_COLS + CONV_DIM + d];
        g_y[(size_t)t * CONV_DIM + d] = __float2half_rn(c * conv);

        int pos = pos0 + i;
        if (pos >= SEQ_LEN - (KSZ - 1)) {
            int seq = t >> 12;
            int r   = pos - (SEQ_LEN - (KSZ - 1));
            states_out[((size_t)seq * (KSZ - 1) + r) * CONV_DIM + d] = bx;
        }
        h0 = h1; h1 = h2; h2 = bx;
    }
}

// ---------------- launch -----------------------------------------------------
extern "C" void kernel_launch(void* const* d_in, const int* in_sizes, int n_in,
                              void* d_out, int out_size)
{
    const float* hidden = (const float*)d_in[0];
    const float* w_in   = (const float*)d_in[1];
    const float* convw  = (const float*)d_in[2];
    const float* w_out  = (const float*)d_in[3];
    float* out = (float*)d_out;

    float* bcx; __half *ha, *w1, *w2, *y;
    cudaGetSymbolAddress((void**)&bcx, g_bcx);
    cudaGetSymbolAddress((void**)&ha,  g_ha);
    cudaGetSymbolAddress((void**)&w1,  g_w1);
    cudaGetSymbolAddress((void**)&w2,  g_w2);
    cudaGetSymbolAddress((void**)&y,   g_y);

    cudaFuncSetAttribute(gemm_f16, cudaFuncAttributeMaxDynamicSharedMemorySize, GSMEM_TOTAL);

    // 0) fp16 conversions
    {
        int n4 = NTOK * KDIM / 4;
        cvt_f16_kernel<<<n4 / 256, 256>>>(hidden, ha, n4);
        n4 = BCX_COLS * KDIM / 4;
        cvt_f16_kernel<<<n4 / 256, 256>>>(w_in, w1, n4);
        n4 = HIDDEN * KDIM / 4;
        cvt_f16_kernel<<<n4 / 256, 256>>>(w_out, w2, n4);
    }

    // 1) GEMM1: bcx = hidden @ w_in^T  [16384 x 6144]
    gemm_f16<<<dim3(BCX_COLS / BN, NTOK / BM), 128, GSMEM_TOTAL>>>(ha, w1, bcx, BCX_COLS);

    // 2) conv + gates + states (+ fp16 y)
    conv_gate_kernel<<<dim3(CONV_DIM / 256, NTOK / TPER), 256>>>(convw, out + (size_t)NTOK * HIDDEN);

    // 3) GEMM2: out = y @ w_out^T  [16384 x 2048]
    gemm_f16<<<dim3(HIDDEN / BN, NTOK / BM), 128, GSMEM_TOTAL>>>(y, w2, out, HIDDEN);
}

// round 9
// speedup vs baseline: 7.6714x; 1.0205x over previous
#include <cuda_runtime.h>
#include <cuda_fp16.h>
#include <stdint.h>

#define NUM_SEQS 4
#define SEQ_LEN  4096
#define NTOK     16384
#define HIDDEN   2048
#define CONV_DIM 2048
#define KSZ      4
#define BCX_COLS 6144
#define KDIM     2048

// ---------------- scratch (static device globals; allocation-free) ----------
__device__ float g_bx[(size_t)NTOK * CONV_DIM];      // gated input b*x (fp32)
__device__ float g_c[(size_t)NTOK * CONV_DIM];       // c gate (fp32)
__device__ __half g_ha[(size_t)NTOK * KDIM];         // fp16 hidden
__device__ __half g_w1p[(size_t)BCX_COLS * KDIM];    // fp16 w_in, rows permuted:
                                                     //  [0,4096): interleaved b,x ; [4096,6144): c
__device__ __half g_w2[(size_t)HIDDEN * KDIM];       // fp16 w_out
__device__ __half g_y[(size_t)NTOK * KDIM];          // fp16 y

// ---------------- ptx helpers (baseline ISA only) ----------------------------
__device__ __forceinline__ uint32_t smem_u32(const void* p) {
    uint32_t a;
    asm("{ .reg .u64 t; cvta.to.shared.u64 t, %1; cvt.u32.u64 %0, t; }" : "=r"(a) : "l"(p));
    return a;
}
__device__ __forceinline__ void cpasync16(uint32_t dst, const void* src) {
    asm volatile("cp.async.cg.shared.global [%0], [%1], 16;" :: "r"(dst), "l"(src));
}
__device__ __forceinline__ void cp_commit() { asm volatile("cp.async.commit_group;" ::: "memory"); }
__device__ __forceinline__ void cp_wait2()  { asm volatile("cp.async.wait_group 2;" ::: "memory"); }

#define LDSM4(r, addr)                                                      \
    asm volatile("ldmatrix.sync.aligned.m8n8.x4.shared.b16 {%0,%1,%2,%3}, [%4];" \
        : "=r"((r)[0]), "=r"((r)[1]), "=r"((r)[2]), "=r"((r)[3]) : "r"(addr))

#define MMAF16(acc, a, b0r, b1r)                                            \
    asm volatile("mma.sync.aligned.m16n8k16.row.col.f32.f16.f16.f32 "       \
        "{%0,%1,%2,%3}, {%4,%5,%6,%7}, {%8,%9}, {%0,%1,%2,%3};"             \
        : "+f"((acc)[0]), "+f"((acc)[1]), "+f"((acc)[2]), "+f"((acc)[3])    \
        : "r"((a)[0]), "r"((a)[1]), "r"((a)[2]), "r"((a)[3]),               \
          "r"(b0r), "r"(b1r))

__device__ __forceinline__ uint32_t swz64(uint32_t off) { return off ^ ((off >> 3) & 0x30); }

// ---------------- fp16 GEMM: C = A[M,K] @ B[N,K]^T --------------------------
// CTA 128x128, 4 warps (2x2), warp tile 64x64, BK=32 halves, 4-stage, 2 CTA/SM
// mode 0: plain fp32 C [M, ldC]
// mode 1: cols are interleaved (b,x) pairs -> writes bx=b*x to C [M, ldC],
//         and writes final-state rows (pos>=4093) to states.
#define BM 128
#define BN 128
#define BKC 32
#define NC (KDIM / BKC)              // 64
#define OFF_A 0
#define OFF_B 8192
#define STAGE_BYTES 16384
#define GSMEM_TOTAL (4 * STAGE_BYTES)   // 64KB

__global__ __launch_bounds__(128, 2)
void gemm_f16(const __half* __restrict__ A, const __half* __restrict__ B,
              float* __restrict__ C, int ldC, int mode, float* __restrict__ states)
{
    extern __shared__ char smem[];
    const uint32_t sbase = smem_u32(smem);
    const int tid  = threadIdx.x;
    const int lane = tid & 31;
    const int wid  = tid >> 5;
    const int wm   = wid >> 1;
    const int wn   = wid & 1;
    const int m0 = blockIdx.y * BM;
    const int n0 = blockIdx.x * BN;

    const __half* gA = A + (size_t)m0 * KDIM;
    const __half* gB = B + (size_t)n0 * KDIM;

    uint32_t aRow[4], aXor[4];
#pragma unroll
    for (int mt = 0; mt < 4; mt++) {
        uint32_t r = wm * 64 + mt * 16 + (lane & 15);
        aRow[mt] = r * 64;
        aXor[mt] = (aRow[mt] >> 3) & 0x30;
    }
    const uint32_t aS = (lane >> 4);
    uint32_t bRow[4], bXor[4];
#pragma unroll
    for (int p = 0; p < 4; p++) {
        uint32_t r = wn * 64 + p * 16 + (lane & 7) + ((lane >> 4) << 3);
        bRow[p] = r * 64;
        bXor[p] = (bRow[p] >> 3) & 0x30;
    }
    const uint32_t bS = ((lane >> 3) & 1);

    float acc[4][8][4];
#pragma unroll
    for (int i = 0; i < 4; i++)
#pragma unroll
        for (int j = 0; j < 8; j++)
#pragma unroll
            for (int q = 0; q < 4; q++) acc[i][j][q] = 0.0f;

    auto load_chunk = [&](int c, int st) {
        const uint32_t stg = sbase + st * STAGE_BYTES;
        const int koff = c * BKC;
#pragma unroll
        for (int p = 0; p < 4; p++) {
            int u = p * 128 + tid;
            int r = u >> 2, s = u & 3;
            cpasync16(stg + OFF_A + swz64((uint32_t)(r * 64 + s * 16)),
                      gA + (size_t)r * KDIM + koff + s * 8);
        }
#pragma unroll
        for (int p = 0; p < 4; p++) {
            int u = p * 128 + tid;
            int r = u >> 2, s = u & 3;
            cpasync16(stg + OFF_B + swz64((uint32_t)(r * 64 + s * 16)),
                      gB + (size_t)r * KDIM + koff + s * 8);
        }
    };

    // prologue: stages 0,1,2
    load_chunk(0, 0); cp_commit();
    load_chunk(1, 1); cp_commit();
    load_chunk(2, 2); cp_commit();
    cp_wait2();
    __syncthreads();

    for (int ch = 0; ch < NC; ch++) {
        if (ch + 3 < NC) load_chunk(ch + 3, (ch + 3) & 3);
        cp_commit();

        const uint32_t stg = sbase + (ch & 3) * STAGE_BYTES;
#pragma unroll
        for (int q = 0; q < 2; q++) {
            const uint32_t s_a = (q * 2 + aS) * 16;
            const uint32_t s_b = (q * 2 + bS) * 16;
            uint32_t af[4][4], bf[4][4];
#pragma unroll
            for (int mt = 0; mt < 4; mt++)
                LDSM4(af[mt], stg + OFF_A + aRow[mt] + (s_a ^ aXor[mt]));
#pragma unroll
            for (int p = 0; p < 4; p++)
                LDSM4(bf[p], stg + OFF_B + bRow[p] + (s_b ^ bXor[p]));
#pragma unroll
            for (int mt = 0; mt < 4; mt++) {
#pragma unroll
                for (int nt = 0; nt < 8; nt++) {
                    const int p = nt >> 1, bi = (nt & 1) * 2;
                    MMAF16(acc[mt][nt], af[mt], bf[p][bi], bf[p][bi + 1]);
                }
            }
        }
        cp_wait2();
        __syncthreads();
    }

    if (mode == 0) {
        const int rw = m0 + wm * 64 + (lane >> 2);
        const int cw = n0 + wn * 64 + (lane & 3) * 2;
#pragma unroll
        for (int mt = 0; mt < 4; mt++) {
#pragma unroll
            for (int nt = 0; nt < 8; nt++) {
                float* p0 = C + (size_t)(rw + mt * 16) * ldC + cw + nt * 8;
                float* p1 = C + (size_t)(rw + mt * 16 + 8) * ldC + cw + nt * 8;
                *(float2*)p0 = make_float2(acc[mt][nt][0], acc[mt][nt][1]);
                *(float2*)p1 = make_float2(acc[mt][nt][2], acc[mt][nt][3]);
            }
        }
    } else {
        // interleaved (b,x): acc cols (2i, 2i+1) = (b_i, x_i); bx col = i
        const int rw0  = m0 + wm * 64 + (lane >> 2);
        const int colb = (n0 >> 1) + wn * 32 + (lane & 3);
#pragma unroll
        for (int mt = 0; mt < 4; mt++) {
#pragma unroll
            for (int nt = 0; nt < 8; nt++) {
                int col = colb + nt * 4;
                int r0 = rw0 + mt * 16;
                int r1 = r0 + 8;
                float p0 = acc[mt][nt][0] * acc[mt][nt][1];
                float p1 = acc[mt][nt][2] * acc[mt][nt][3];
                C[(size_t)r0 * ldC + col] = p0;
                C[(size_t)r1 * ldC + col] = p1;
                int pos0 = r0 & (SEQ_LEN - 1);
                if (pos0 >= SEQ_LEN - (KSZ - 1))
                    states[((size_t)(r0 >> 12) * (KSZ - 1) + (pos0 - (SEQ_LEN - 3))) * CONV_DIM + col] = p0;
                int pos1 = r1 & (SEQ_LEN - 1);
                if (pos1 >= SEQ_LEN - (KSZ - 1))
                    states[((size_t)(r1 >> 12) * (KSZ - 1) + (pos1 - (SEQ_LEN - 3))) * CONV_DIM + col] = p1;
            }
        }
    }
}

// ---------------- fp32 -> fp16 converts -------------------------------------
__global__ __launch_bounds__(256)
void cvt_f16_kernel(const float* __restrict__ in, __half* __restrict__ out, int n4)
{
    int i = blockIdx.x * blockDim.x + threadIdx.x;
    if (i >= n4) return;
    float4 v = ((const float4*)in)[i];
    ((__half2*)out)[i * 2 + 0] = __floats2half2_rn(v.x, v.y);
    ((__half2*)out)[i * 2 + 1] = __floats2half2_rn(v.z, v.w);
}

// permuted convert for w_in: out row r -> src row
//   r < 4096 : (r>>1) + ((r&1) ? 4096 : 0)   (interleaved b,x)
//   r >= 4096: r - 2048                       (c plane)
__global__ __launch_bounds__(256)
void cvt_w1_kernel(const float* __restrict__ w_in, __half* __restrict__ out)
{
    int i = blockIdx.x * blockDim.x + threadIdx.x;   // element/4 index
    int n4 = BCX_COLS * KDIM / 4;
    if (i >= n4) return;
    int r = (i * 4) / KDIM;
    int k = (i * 4) % KDIM;
    int src = (r < 4096) ? ((r >> 1) + ((r & 1) ? 4096 : 0)) : (r - 2048);
    float4 v = *(const float4*)(w_in + (size_t)src * KDIM + k);
    ((__half2*)out)[i * 2 + 0] = __floats2half2_rn(v.x, v.y);
    ((__half2*)out)[i * 2 + 1] = __floats2half2_rn(v.z, v.w);
}

// ---------------- gate + causal conv (bx, c precomputed); y -> fp16 ---------
#define TPER 8
__global__ __launch_bounds__(256)
void conv_gate_kernel(const float* __restrict__ cw)
{
    int d  = blockIdx.x * blockDim.x + threadIdx.x;
    int t0 = blockIdx.y * TPER;
    int pos0 = t0 & (SEQ_LEN - 1);

    float w0 = cw[d * KSZ + 0];
    float w1 = cw[d * KSZ + 1];
    float w2 = cw[d * KSZ + 2];
    float w3 = cw[d * KSZ + 3];

    float h0 = 0.f, h1 = 0.f, h2 = 0.f;
    if (pos0 >= 3) h0 = g_bx[(size_t)(t0 - 3) * CONV_DIM + d];
    if (pos0 >= 2) h1 = g_bx[(size_t)(t0 - 2) * CONV_DIM + d];
    if (pos0 >= 1) h2 = g_bx[(size_t)(t0 - 1) * CONV_DIM + d];

#pragma unroll
    for (int i = 0; i < TPER; i++) {
        int t = t0 + i;
        float bx = g_bx[(size_t)t * CONV_DIM + d];
        float conv = fmaf(w0, h0, fmaf(w1, h1, fmaf(w2, h2, w3 * bx)));
        float c = g_c[(size_t)t * CONV_DIM + d];
        g_y[(size_t)t * CONV_DIM + d] = __float2half_rn(c * conv);
        h0 = h1; h1 = h2; h2 = bx;
    }
}

// ---------------- launch -----------------------------------------------------
extern "C" void kernel_launch(void* const* d_in, const int* in_sizes, int n_in,
                              void* d_out, int out_size)
{
    const float* hidden = (const float*)d_in[0];
    const float* w_in   = (const float*)d_in[1];
    const float* convw  = (const float*)d_in[2];
    const float* w_out  = (const float*)d_in[3];
    float* out = (float*)d_out;
    float* states = out + (size_t)NTOK * HIDDEN;

    float *bx, *cbuf; __half *ha, *w1p, *w2, *y;
    cudaGetSymbolAddress((void**)&bx,   g_bx);
    cudaGetSymbolAddress((void**)&cbuf, g_c);
    cudaGetSymbolAddress((void**)&ha,   g_ha);
    cudaGetSymbolAddress((void**)&w1p,  g_w1p);
    cudaGetSymbolAddress((void**)&w2,   g_w2);
    cudaGetSymbolAddress((void**)&y,    g_y);

    cudaFuncSetAttribute(gemm_f16, cudaFuncAttributeMaxDynamicSharedMemorySize, GSMEM_TOTAL);

    // 0) fp16 conversions (w_in permuted)
    {
        int n4 = NTOK * KDIM / 4;
        cvt_f16_kernel<<<n4 / 256, 256>>>(hidden, ha, n4);
        n4 = BCX_COLS * KDIM / 4;
        cvt_w1_kernel<<<n4 / 256, 256>>>(w_in, w1p);
        n4 = HIDDEN * KDIM / 4;
        cvt_f16_kernel<<<n4 / 256, 256>>>(w_out, w2, n4);
    }

    // 1a) GEMM (interleaved b,x): bx = b*x, + states   [N=4096 -> 2048 cols]
    gemm_f16<<<dim3(4096 / BN, NTOK / BM), 128, GSMEM_TOTAL>>>(
        ha, w1p, bx, CONV_DIM, 1, states);

    // 1b) GEMM: c = hidden @ w_c^T   [N=2048]
    gemm_f16<<<dim3(HIDDEN / BN, NTOK / BM), 128, GSMEM_TOTAL>>>(
        ha, w1p + (size_t)4096 * KDIM, cbuf, CONV_DIM, 0, nullptr);

    // 2) conv + BCx gate -> y (fp16)
    conv_gate_kernel<<<dim3(CONV_DIM / 256, NTOK / TPER), 256>>>(convw);

    // 3) GEMM2: out = y @ w_out^T
    gemm_f16<<<dim3(HIDDEN / BN, NTOK / BM), 128, GSMEM_TOTAL>>>(
        y, w2, out, HIDDEN, 0, nullptr);
}

// round 11
// speedup vs baseline: 7.7037x; 1.0042x over previous
#include <cuda_runtime.h>
#include <cuda_fp16.h>
#include <stdint.h>

#define NUM_SEQS 4
#define SEQ_LEN  4096
#define NTOK     16384
#define HIDDEN   2048
#define CONV_DIM 2048
#define KSZ      4
#define BCX_COLS 6144
#define KDIM     2048

// ---------------- scratch (static device globals; allocation-free) ----------
__device__ float g_bx[(size_t)NTOK * CONV_DIM];      // gated input b*x (fp32)
__device__ float g_c[(size_t)NTOK * CONV_DIM];       // c gate (fp32)
__device__ __half g_ha[(size_t)NTOK * KDIM];         // fp16 hidden
__device__ __half g_w1p[(size_t)BCX_COLS * KDIM];    // fp16 w_in, rows permuted:
                                                     //  [0,4096): interleaved b,x ; [4096,6144): c
__device__ __half g_w2[(size_t)HIDDEN * KDIM];       // fp16 w_out
__device__ __half g_y[(size_t)NTOK * KDIM];          // fp16 y

// ---------------- ptx helpers (baseline ISA only) ----------------------------
__device__ __forceinline__ uint32_t smem_u32(const void* p) {
    uint32_t a;
    asm("{ .reg .u64 t; cvta.to.shared.u64 t, %1; cvt.u32.u64 %0, t; }" : "=r"(a) : "l"(p));
    return a;
}
__device__ __forceinline__ void cpasync16(uint32_t dst, const void* src) {
    asm volatile("cp.async.cg.shared.global [%0], [%1], 16;" :: "r"(dst), "l"(src));
}
__device__ __forceinline__ void cp_commit() { asm volatile("cp.async.commit_group;" ::: "memory"); }
__device__ __forceinline__ void cp_wait2()  { asm volatile("cp.async.wait_group 2;" ::: "memory"); }

#define LDSM4(r, addr)                                                      \
    asm volatile("ldmatrix.sync.aligned.m8n8.x4.shared.b16 {%0,%1,%2,%3}, [%4];" \
        : "=r"((r)[0]), "=r"((r)[1]), "=r"((r)[2]), "=r"((r)[3]) : "r"(addr))

#define MMAF16(acc, a, b0r, b1r)                                            \
    asm volatile("mma.sync.aligned.m16n8k16.row.col.f32.f16.f16.f32 "       \
        "{%0,%1,%2,%3}, {%4,%5,%6,%7}, {%8,%9}, {%0,%1,%2,%3};"             \
        : "+f"((acc)[0]), "+f"((acc)[1]), "+f"((acc)[2]), "+f"((acc)[3])    \
        : "r"((a)[0]), "r"((a)[1]), "r"((a)[2]), "r"((a)[3]),               \
          "r"(b0r), "r"(b1r))

__device__ __forceinline__ uint32_t swz64(uint32_t off) { return off ^ ((off >> 3) & 0x30); }

// ---------------- fp16 GEMM: C = A[M,K] @ B[N,K]^T --------------------------
// CTA 128x128, 4 warps (2x2), warp tile 64x64, BK=32 halves, 4-stage,
// double-buffered register fragments (barrier-correct), 2 CTAs/SM.
#define BM 128
#define BN 128
#define BKC 32
#define NC (KDIM / BKC)              // 64
#define OFF_A 0
#define OFF_B 8192
#define STAGE_BYTES 16384
#define GSMEM_TOTAL (4 * STAGE_BYTES)   // 64KB

__global__ __launch_bounds__(128, 2)
void gemm_f16(const __half* __restrict__ A, const __half* __restrict__ B,
              float* __restrict__ C, int ldC, int mode, float* __restrict__ states)
{
    extern __shared__ char smem[];
    const uint32_t sbase = smem_u32(smem);
    const int tid  = threadIdx.x;
    const int lane = tid & 31;
    const int wid  = tid >> 5;
    const int wm   = wid >> 1;
    const int wn   = wid & 1;
    const int m0 = blockIdx.y * BM;
    const int n0 = blockIdx.x * BN;

    const __half* gA = A + (size_t)m0 * KDIM;
    const __half* gB = B + (size_t)n0 * KDIM;

    uint32_t aRow[4], aXor[4];
#pragma unroll
    for (int mt = 0; mt < 4; mt++) {
        uint32_t r = wm * 64 + mt * 16 + (lane & 15);
        aRow[mt] = r * 64;
        aXor[mt] = (aRow[mt] >> 3) & 0x30;
    }
    const uint32_t aS = (lane >> 4);
    uint32_t bRow[4], bXor[4];
#pragma unroll
    for (int p = 0; p < 4; p++) {
        uint32_t r = wn * 64 + p * 16 + (lane & 7) + ((lane >> 4) << 3);
        bRow[p] = r * 64;
        bXor[p] = (bRow[p] >> 3) & 0x30;
    }
    const uint32_t bS = ((lane >> 3) & 1);

    float acc[4][8][4];
#pragma unroll
    for (int i = 0; i < 4; i++)
#pragma unroll
        for (int j = 0; j < 8; j++)
#pragma unroll
            for (int q = 0; q < 4; q++) acc[i][j][q] = 0.0f;

    auto load_chunk = [&](int c, int st) {
        const uint32_t stg = sbase + st * STAGE_BYTES;
        const int koff = c * BKC;
#pragma unroll
        for (int p = 0; p < 4; p++) {
            int u = p * 128 + tid;
            int r = u >> 2, s = u & 3;
            cpasync16(stg + OFF_A + swz64((uint32_t)(r * 64 + s * 16)),
                      gA + (size_t)r * KDIM + koff + s * 8);
        }
#pragma unroll
        for (int p = 0; p < 4; p++) {
            int u = p * 128 + tid;
            int r = u >> 2, s = u & 3;
            cpasync16(stg + OFF_B + swz64((uint32_t)(r * 64 + s * 16)),
                      gB + (size_t)r * KDIM + koff + s * 8);
        }
    };

    uint32_t af0[4][4], bf0[4][4], af1[4][4], bf1[4][4];

    auto ldsm_set = [&](uint32_t stg, int q, uint32_t af[4][4], uint32_t bf[4][4]) {
        const uint32_t s_a = (q * 2 + aS) * 16;
        const uint32_t s_b = (q * 2 + bS) * 16;
#pragma unroll
        for (int mt = 0; mt < 4; mt++)
            LDSM4(af[mt], stg + OFF_A + aRow[mt] + (s_a ^ aXor[mt]));
#pragma unroll
        for (int p = 0; p < 4; p++)
            LDSM4(bf[p], stg + OFF_B + bRow[p] + (s_b ^ bXor[p]));
    };

    auto mma_set = [&](uint32_t af[4][4], uint32_t bf[4][4]) {
#pragma unroll
        for (int mt = 0; mt < 4; mt++) {
#pragma unroll
            for (int nt = 0; nt < 8; nt++) {
                const int p = nt >> 1, bi = (nt & 1) * 2;
                MMAF16(acc[mt][nt], af[mt], bf[p][bi], bf[p][bi + 1]);
            }
        }
    };

    // prologue: stages 0,1,2
    load_chunk(0, 0); cp_commit();
    load_chunk(1, 1); cp_commit();
    load_chunk(2, 2); cp_commit();
    cp_wait2();                        // own groups for chunk 0 done
    __syncthreads();                   // all threads' chunk-0 fills visible
    ldsm_set(sbase, 0, af0, bf0);      // chunk 0, q0

    for (int ch = 0; ch < NC; ch++) {
        const uint32_t stg = sbase + (ch & 3) * STAGE_BYTES;
        if (ch + 3 < NC) load_chunk(ch + 3, (ch + 3) & 3);
        cp_commit();

        ldsm_set(stg, 1, af1, bf1);    // q1 frags; latency hidden under q0 MMAs
        mma_set(af0, bf0);
        mma_set(af1, bf1);

        cp_wait2();                    // own groups for chunk ch+1 done
        __syncthreads();               // all threads' ch+1 fills visible; stage ch reusable
        if (ch + 1 < NC)
            ldsm_set(sbase + ((ch + 1) & 3) * STAGE_BYTES, 0, af0, bf0);  // next q0
    }

    if (mode == 0) {
        const int rw = m0 + wm * 64 + (lane >> 2);
        const int cw = n0 + wn * 64 + (lane & 3) * 2;
#pragma unroll
        for (int mt = 0; mt < 4; mt++) {
#pragma unroll
            for (int nt = 0; nt < 8; nt++) {
                float* p0 = C + (size_t)(rw + mt * 16) * ldC + cw + nt * 8;
                float* p1 = C + (size_t)(rw + mt * 16 + 8) * ldC + cw + nt * 8;
                *(float2*)p0 = make_float2(acc[mt][nt][0], acc[mt][nt][1]);
                *(float2*)p1 = make_float2(acc[mt][nt][2], acc[mt][nt][3]);
            }
        }
    } else {
        // interleaved (b,x): acc cols (2i, 2i+1) = (b_i, x_i); bx col = i
        const int rw0  = m0 + wm * 64 + (lane >> 2);
        const int colb = (n0 >> 1) + wn * 32 + (lane & 3);
#pragma unroll
        for (int mt = 0; mt < 4; mt++) {
#pragma unroll
            for (int nt = 0; nt < 8; nt++) {
                int col = colb + nt * 4;
                int r0 = rw0 + mt * 16;
                int r1 = r0 + 8;
                float p0 = acc[mt][nt][0] * acc[mt][nt][1];
                float p1 = acc[mt][nt][2] * acc[mt][nt][3];
                C[(size_t)r0 * ldC + col] = p0;
                C[(size_t)r1 * ldC + col] = p1;
                int pos0 = r0 & (SEQ_LEN - 1);
                if (pos0 >= SEQ_LEN - (KSZ - 1))
                    states[((size_t)(r0 >> 12) * (KSZ - 1) + (pos0 - (SEQ_LEN - 3))) * CONV_DIM + col] = p0;
                int pos1 = r1 & (SEQ_LEN - 1);
                if (pos1 >= SEQ_LEN - (KSZ - 1))
                    states[((size_t)(r1 >> 12) * (KSZ - 1) + (pos1 - (SEQ_LEN - 3))) * CONV_DIM + col] = p1;
            }
        }
    }
}

// ---------------- fp32 -> fp16 converts -------------------------------------
__global__ __launch_bounds__(256)
void cvt_f16_kernel(const float* __restrict__ in, __half* __restrict__ out, int n4)
{
    int i = blockIdx.x * blockDim.x + threadIdx.x;
    if (i >= n4) return;
    float4 v = ((const float4*)in)[i];
    ((__half2*)out)[i * 2 + 0] = __floats2half2_rn(v.x, v.y);
    ((__half2*)out)[i * 2 + 1] = __floats2half2_rn(v.z, v.w);
}

// permuted convert for w_in: out row r -> src row
//   r < 4096 : (r>>1) + ((r&1) ? 4096 : 0)   (interleaved b,x)
//   r >= 4096: r - 2048                       (c plane)
__global__ __launch_bounds__(256)
void cvt_w1_kernel(const float* __restrict__ w_in, __half* __restrict__ out)
{
    int i = blockIdx.x * blockDim.x + threadIdx.x;   // element/4 index
    int n4 = BCX_COLS * KDIM / 4;
    if (i >= n4) return;
    int r = (i * 4) / KDIM;
    int k = (i * 4) % KDIM;
    int src = (r < 4096) ? ((r >> 1) + ((r & 1) ? 4096 : 0)) : (r - 2048);
    float4 v = *(const float4*)(w_in + (size_t)src * KDIM + k);
    ((__half2*)out)[i * 2 + 0] = __floats2half2_rn(v.x, v.y);
    ((__half2*)out)[i * 2 + 1] = __floats2half2_rn(v.z, v.w);
}

// ---------------- gate + causal conv (bx, c precomputed); y -> fp16 ---------
#define TPER 8
__global__ __launch_bounds__(256)
void conv_gate_kernel(const float* __restrict__ cw)
{
    int d  = blockIdx.x * blockDim.x + threadIdx.x;
    int t0 = blockIdx.y * TPER;
    int pos0 = t0 & (SEQ_LEN - 1);

    float w0 = cw[d * KSZ + 0];
    float w1 = cw[d * KSZ + 1];
    float w2 = cw[d * KSZ + 2];
    float w3 = cw[d * KSZ + 3];

    float h0 = 0.f, h1 = 0.f, h2 = 0.f;
    if (pos0 >= 3) h0 = g_bx[(size_t)(t0 - 3) * CONV_DIM + d];
    if (pos0 >= 2) h1 = g_bx[(size_t)(t0 - 2) * CONV_DIM + d];
    if (pos0 >= 1) h2 = g_bx[(size_t)(t0 - 1) * CONV_DIM + d];

#pragma unroll
    for (int i = 0; i < TPER; i++) {
        int t = t0 + i;
        float bx = g_bx[(size_t)t * CONV_DIM + d];
        float conv = fmaf(w0, h0, fmaf(w1, h1, fmaf(w2, h2, w3 * bx)));
        float c = g_c[(size_t)t * CONV_DIM + d];
        g_y[(size_t)t * CONV_DIM + d] = __float2half_rn(c * conv);
        h0 = h1; h1 = h2; h2 = bx;
    }
}

// ---------------- launch -----------------------------------------------------
extern "C" void kernel_launch(void* const* d_in, const int* in_sizes, int n_in,
                              void* d_out, int out_size)
{
    const float* hidden = (const float*)d_in[0];
    const float* w_in   = (const float*)d_in[1];
    const float* convw  = (const float*)d_in[2];
    const float* w_out  = (const float*)d_in[3];
    float* out = (float*)d_out;
    float* states = out + (size_t)NTOK * HIDDEN;

    float *bx, *cbuf; __half *ha, *w1p, *w2, *y;
    cudaGetSymbolAddress((void**)&bx,   g_bx);
    cudaGetSymbolAddress((void**)&cbuf, g_c);
    cudaGetSymbolAddress((void**)&ha,   g_ha);
    cudaGetSymbolAddress((void**)&w1p,  g_w1p);
    cudaGetSymbolAddress((void**)&w2,   g_w2);
    cudaGetSymbolAddress((void**)&y,    g_y);

    cudaFuncSetAttribute(gemm_f16, cudaFuncAttributeMaxDynamicSharedMemorySize, GSMEM_TOTAL);

    // 0) fp16 conversions (w_in permuted)
    {
        int n4 = NTOK * KDIM / 4;
        cvt_f16_kernel<<<n4 / 256, 256>>>(hidden, ha, n4);
        n4 = BCX_COLS * KDIM / 4;
        cvt_w1_kernel<<<n4 / 256, 256>>>(w_in, w1p);
        n4 = HIDDEN * KDIM / 4;
        cvt_f16_kernel<<<n4 / 256, 256>>>(w_out, w2, n4);
    }

    // 1a) GEMM (interleaved b,x): bx = b*x, + states   [N=4096 -> 2048 cols]
    gemm_f16<<<dim3(4096 / BN, NTOK / BM), 128, GSMEM_TOTAL>>>(
        ha, w1p, bx, CONV_DIM, 1, states);

    // 1b) GEMM: c = hidden @ w_c^T   [N=2048]
    gemm_f16<<<dim3(HIDDEN / BN, NTOK / BM), 128, GSMEM_TOTAL>>>(
        ha, w1p + (size_t)4096 * KDIM, cbuf, CONV_DIM, 0, nullptr);

    // 2) conv + BCx gate -> y (fp16)
    conv_gate_kernel<<<dim3(CONV_DIM / 256, NTOK / TPER), 256>>>(convw);

    // 3) GEMM2: out = y @ w_out^T
    gemm_f16<<<dim3(HIDDEN / BN, NTOK / BM), 128, GSMEM_TOTAL>>>(
        y, w2, out, HIDDEN, 0, nullptr);
}

// round 12
// speedup vs baseline: 7.8291x; 1.0163x over previous
#include <cuda_runtime.h>
#include <cuda_fp16.h>
#include <stdint.h>

#define NUM_SEQS 4
#define SEQ_LEN  4096
#define NTOK     16384
#define HIDDEN   2048
#define CONV_DIM 2048
#define KSZ      4
#define BCX_COLS 6144
#define KDIM     2048

// ---------------- scratch (static device globals; allocation-free) ----------
__device__ float  g_bx[(size_t)NTOK * CONV_DIM];     // gated input b*x (fp32)
__device__ __half g_ch[(size_t)NTOK * CONV_DIM];     // c gate (fp16)
__device__ __half g_ha[(size_t)NTOK * KDIM];         // fp16 hidden
__device__ __half g_w1p[(size_t)BCX_COLS * KDIM];    // fp16 w_in, rows permuted:
                                                     //  [0,4096): interleaved b,x ; [4096,6144): c
__device__ __half g_w2[(size_t)HIDDEN * KDIM];       // fp16 w_out
__device__ __half g_y[(size_t)NTOK * KDIM];          // fp16 y

// ---------------- ptx helpers (baseline ISA only) ----------------------------
__device__ __forceinline__ uint32_t smem_u32(const void* p) {
    uint32_t a;
    asm("{ .reg .u64 t; cvta.to.shared.u64 t, %1; cvt.u32.u64 %0, t; }" : "=r"(a) : "l"(p));
    return a;
}
__device__ __forceinline__ void cpasync16(uint32_t dst, const void* src) {
    asm volatile("cp.async.cg.shared.global [%0], [%1], 16;" :: "r"(dst), "l"(src));
}
__device__ __forceinline__ void cp_commit() { asm volatile("cp.async.commit_group;" ::: "memory"); }
__device__ __forceinline__ void cp_wait2()  { asm volatile("cp.async.wait_group 2;" ::: "memory"); }

#define LDSM4(r, addr)                                                      \
    asm volatile("ldmatrix.sync.aligned.m8n8.x4.shared.b16 {%0,%1,%2,%3}, [%4];" \
        : "=r"((r)[0]), "=r"((r)[1]), "=r"((r)[2]), "=r"((r)[3]) : "r"(addr))

#define MMAF16(acc, a, b0r, b1r)                                            \
    asm volatile("mma.sync.aligned.m16n8k16.row.col.f32.f16.f16.f32 "       \
        "{%0,%1,%2,%3}, {%4,%5,%6,%7}, {%8,%9}, {%0,%1,%2,%3};"             \
        : "+f"((acc)[0]), "+f"((acc)[1]), "+f"((acc)[2]), "+f"((acc)[3])    \
        : "r"((a)[0]), "r"((a)[1]), "r"((a)[2]), "r"((a)[3]),               \
          "r"(b0r), "r"(b1r))

__device__ __forceinline__ uint32_t swz64(uint32_t off) { return off ^ ((off >> 3) & 0x30); }

// ---------------- fp16 GEMM: C = A[M,K] @ B[N,K]^T --------------------------
// CTA 128x128, 4 warps (2x2), warp tile 64x64, BK=32 halves, 4-stage,
// double-buffered register fragments, 2 CTAs/SM.
// mode 0: plain fp32 C
// mode 1: FUSED in_proj: n0 < 4096 -> interleaved (b,x) -> bx fp32 + states;
//                        n0 >= 4096 -> c plane -> fp16 g_ch at col n0-4096.
#define BM 128
#define BN 128
#define BKC 32
#define NC (KDIM / BKC)              // 64
#define OFF_A 0
#define OFF_B 8192
#define STAGE_BYTES 16384
#define GSMEM_TOTAL (4 * STAGE_BYTES)   // 64KB

__global__ __launch_bounds__(128, 2)
void gemm_f16(const __half* __restrict__ A, const __half* __restrict__ B,
              float* __restrict__ C, int ldC, int mode, float* __restrict__ states)
{
    extern __shared__ char smem[];
    const uint32_t sbase = smem_u32(smem);
    const int tid  = threadIdx.x;
    const int lane = tid & 31;
    const int wid  = tid >> 5;
    const int wm   = wid >> 1;
    const int wn   = wid & 1;
    const int m0 = blockIdx.y * BM;
    const int n0 = blockIdx.x * BN;

    const __half* gA = A + (size_t)m0 * KDIM;
    const __half* gB = B + (size_t)n0 * KDIM;

    uint32_t aRow[4], aXor[4];
#pragma unroll
    for (int mt = 0; mt < 4; mt++) {
        uint32_t r = wm * 64 + mt * 16 + (lane & 15);
        aRow[mt] = r * 64;
        aXor[mt] = (aRow[mt] >> 3) & 0x30;
    }
    const uint32_t aS = (lane >> 4);
    uint32_t bRow[4], bXor[4];
#pragma unroll
    for (int p = 0; p < 4; p++) {
        uint32_t r = wn * 64 + p * 16 + (lane & 7) + ((lane >> 4) << 3);
        bRow[p] = r * 64;
        bXor[p] = (bRow[p] >> 3) & 0x30;
    }
    const uint32_t bS = ((lane >> 3) & 1);

    float acc[4][8][4];
#pragma unroll
    for (int i = 0; i < 4; i++)
#pragma unroll
        for (int j = 0; j < 8; j++)
#pragma unroll
            for (int q = 0; q < 4; q++) acc[i][j][q] = 0.0f;

    auto load_chunk = [&](int c, int st) {
        const uint32_t stg = sbase + st * STAGE_BYTES;
        const int koff = c * BKC;
#pragma unroll
        for (int p = 0; p < 4; p++) {
            int u = p * 128 + tid;
            int r = u >> 2, s = u & 3;
            cpasync16(stg + OFF_A + swz64((uint32_t)(r * 64 + s * 16)),
                      gA + (size_t)r * KDIM + koff + s * 8);
        }
#pragma unroll
        for (int p = 0; p < 4; p++) {
            int u = p * 128 + tid;
            int r = u >> 2, s = u & 3;
            cpasync16(stg + OFF_B + swz64((uint32_t)(r * 64 + s * 16)),
                      gB + (size_t)r * KDIM + koff + s * 8);
        }
    };

    uint32_t af0[4][4], bf0[4][4], af1[4][4], bf1[4][4];

    auto ldsm_set = [&](uint32_t stg, int q, uint32_t af[4][4], uint32_t bf[4][4]) {
        const uint32_t s_a = (q * 2 + aS) * 16;
        const uint32_t s_b = (q * 2 + bS) * 16;
#pragma unroll
        for (int mt = 0; mt < 4; mt++)
            LDSM4(af[mt], stg + OFF_A + aRow[mt] + (s_a ^ aXor[mt]));
#pragma unroll
        for (int p = 0; p < 4; p++)
            LDSM4(bf[p], stg + OFF_B + bRow[p] + (s_b ^ bXor[p]));
    };

    auto mma_set = [&](uint32_t af[4][4], uint32_t bf[4][4]) {
#pragma unroll
        for (int mt = 0; mt < 4; mt++) {
#pragma unroll
            for (int nt = 0; nt < 8; nt++) {
                const int p = nt >> 1, bi = (nt & 1) * 2;
                MMAF16(acc[mt][nt], af[mt], bf[p][bi], bf[p][bi + 1]);
            }
        }
    };

    // prologue: stages 0,1,2
    load_chunk(0, 0); cp_commit();
    load_chunk(1, 1); cp_commit();
    load_chunk(2, 2); cp_commit();
    cp_wait2();
    __syncthreads();
    ldsm_set(sbase, 0, af0, bf0);

    for (int ch = 0; ch < NC; ch++) {
        const uint32_t stg = sbase + (ch & 3) * STAGE_BYTES;
        if (ch + 3 < NC) load_chunk(ch + 3, (ch + 3) & 3);
        cp_commit();

        ldsm_set(stg, 1, af1, bf1);
        mma_set(af0, bf0);
        mma_set(af1, bf1);

        cp_wait2();
        __syncthreads();
        if (ch + 1 < NC)
            ldsm_set(sbase + ((ch + 1) & 3) * STAGE_BYTES, 0, af0, bf0);
    }

    if (mode == 0) {
        const int rw = m0 + wm * 64 + (lane >> 2);
        const int cw = n0 + wn * 64 + (lane & 3) * 2;
#pragma unroll
        for (int mt = 0; mt < 4; mt++) {
#pragma unroll
            for (int nt = 0; nt < 8; nt++) {
                float* p0 = C + (size_t)(rw + mt * 16) * ldC + cw + nt * 8;
                float* p1 = C + (size_t)(rw + mt * 16 + 8) * ldC + cw + nt * 8;
                *(float2*)p0 = make_float2(acc[mt][nt][0], acc[mt][nt][1]);
                *(float2*)p1 = make_float2(acc[mt][nt][2], acc[mt][nt][3]);
            }
        }
    } else if (n0 < 4096) {
        // interleaved (b,x): acc cols (2i, 2i+1) = (b_i, x_i); bx col = i
        const int rw0  = m0 + wm * 64 + (lane >> 2);
        const int colb = (n0 >> 1) + wn * 32 + (lane & 3);
#pragma unroll
        for (int mt = 0; mt < 4; mt++) {
#pragma unroll
            for (int nt = 0; nt < 8; nt++) {
                int col = colb + nt * 4;
                int r0 = rw0 + mt * 16;
                int r1 = r0 + 8;
                float p0 = acc[mt][nt][0] * acc[mt][nt][1];
                float p1 = acc[mt][nt][2] * acc[mt][nt][3];
                C[(size_t)r0 * ldC + col] = p0;
                C[(size_t)r1 * ldC + col] = p1;
                int pos0 = r0 & (SEQ_LEN - 1);
                if (pos0 >= SEQ_LEN - (KSZ - 1))
                    states[((size_t)(r0 >> 12) * (KSZ - 1) + (pos0 - (SEQ_LEN - 3))) * CONV_DIM + col] = p0;
                int pos1 = r1 & (SEQ_LEN - 1);
                if (pos1 >= SEQ_LEN - (KSZ - 1))
                    states[((size_t)(r1 >> 12) * (KSZ - 1) + (pos1 - (SEQ_LEN - 3))) * CONV_DIM + col] = p1;
            }
        }
    } else {
        // c plane -> fp16 g_ch, col = n0 - 4096
        const int rw = m0 + wm * 64 + (lane >> 2);
        const int cw = (n0 - 4096) + wn * 64 + (lane & 3) * 2;
#pragma unroll
        for (int mt = 0; mt < 4; mt++) {
#pragma unroll
            for (int nt = 0; nt < 8; nt++) {
                __half2* p0 = (__half2*)&g_ch[(size_t)(rw + mt * 16) * CONV_DIM + cw + nt * 8];
                __half2* p1 = (__half2*)&g_ch[(size_t)(rw + mt * 16 + 8) * CONV_DIM + cw + nt * 8];
                *p0 = __floats2half2_rn(acc[mt][nt][0], acc[mt][nt][1]);
                *p1 = __floats2half2_rn(acc[mt][nt][2], acc[mt][nt][3]);
            }
        }
    }
}

// ---------------- fused fp32 -> fp16 converts (hidden | w_in permuted | w_out)
#define N4_HA (NTOK * KDIM / 4)
#define N4_W1 (BCX_COLS * KDIM / 4)
#define N4_W2 (HIDDEN * KDIM / 4)

__global__ __launch_bounds__(256)
void cvt_all_kernel(const float* __restrict__ hidden, const float* __restrict__ w_in,
                    const float* __restrict__ w_out)
{
    int i = blockIdx.x * blockDim.x + threadIdx.x;
    const float* src;
    __half* dst;
    int j;
    if (i < N4_HA) {
        j = i; src = hidden; dst = g_ha;
    } else if (i < N4_HA + N4_W1) {
        j = i - N4_HA;
        int r = (j * 4) / KDIM, k = (j * 4) % KDIM;
        int sr = (r < 4096) ? ((r >> 1) + ((r & 1) ? 4096 : 0)) : (r - 2048);
        float4 v = *(const float4*)(w_in + (size_t)sr * KDIM + k);
        ((__half2*)g_w1p)[j * 2 + 0] = __floats2half2_rn(v.x, v.y);
        ((__half2*)g_w1p)[j * 2 + 1] = __floats2half2_rn(v.z, v.w);
        return;
    } else if (i < N4_HA + N4_W1 + N4_W2) {
        j = i - N4_HA - N4_W1; src = w_out; dst = g_w2;
    } else return;
    float4 v = ((const float4*)src)[j];
    ((__half2*)dst)[j * 2 + 0] = __floats2half2_rn(v.x, v.y);
    ((__half2*)dst)[j * 2 + 1] = __floats2half2_rn(v.z, v.w);
}

// ---------------- causal conv + BCx gate (bx f32, c f16); y -> fp16 ---------
#define TPER 8
__global__ __launch_bounds__(256)
void conv_gate_kernel(const float* __restrict__ cw)
{
    int d  = blockIdx.x * blockDim.x + threadIdx.x;
    int t0 = blockIdx.y * TPER;
    int pos0 = t0 & (SEQ_LEN - 1);

    float w0 = cw[d * KSZ + 0];
    float w1 = cw[d * KSZ + 1];
    float w2 = cw[d * KSZ + 2];
    float w3 = cw[d * KSZ + 3];

    float h0 = 0.f, h1 = 0.f, h2 = 0.f;
    if (pos0 >= 3) h0 = g_bx[(size_t)(t0 - 3) * CONV_DIM + d];
    if (pos0 >= 2) h1 = g_bx[(size_t)(t0 - 2) * CONV_DIM + d];
    if (pos0 >= 1) h2 = g_bx[(size_t)(t0 - 1) * CONV_DIM + d];

#pragma unroll
    for (int i = 0; i < TPER; i++) {
        int t = t0 + i;
        float bx = g_bx[(size_t)t * CONV_DIM + d];
        float conv = fmaf(w0, h0, fmaf(w1, h1, fmaf(w2, h2, w3 * bx)));
        float c = __half2float(g_ch[(size_t)t * CONV_DIM + d]);
        g_y[(size_t)t * CONV_DIM + d] = __float2half_rn(c * conv);
        h0 = h1; h1 = h2; h2 = bx;
    }
}

// ---------------- launch -----------------------------------------------------
extern "C" void kernel_launch(void* const* d_in, const int* in_sizes, int n_in,
                              void* d_out, int out_size)
{
    const float* hidden = (const float*)d_in[0];
    const float* w_in   = (const float*)d_in[1];
    const float* convw  = (const float*)d_in[2];
    const float* w_out  = (const float*)d_in[3];
    float* out = (float*)d_out;
    float* states = out + (size_t)NTOK * HIDDEN;

    float* bx; __half *ha, *w1p, *w2, *y;
    cudaGetSymbolAddress((void**)&bx,  g_bx);
    cudaGetSymbolAddress((void**)&ha,  g_ha);
    cudaGetSymbolAddress((void**)&w1p, g_w1p);
    cudaGetSymbolAddress((void**)&w2,  g_w2);
    cudaGetSymbolAddress((void**)&y,   g_y);

    cudaFuncSetAttribute(gemm_f16, cudaFuncAttributeMaxDynamicSharedMemorySize, GSMEM_TOTAL);

    // 0) fused fp16 conversions
    {
        int total = N4_HA + N4_W1 + N4_W2;
        cvt_all_kernel<<<(total + 255) / 256, 256>>>(hidden, w_in, w_out);
    }

    // 1) FUSED in_proj GEMM: bx=b*x (+states) AND c-plane (fp16), one launch
    gemm_f16<<<dim3(BCX_COLS / BN, NTOK / BM), 128, GSMEM_TOTAL>>>(
        ha, w1p, bx, CONV_DIM, 1, states);

    // 2) conv + BCx gate -> y (fp16)
    conv_gate_kernel<<<dim3(CONV_DIM / 256, NTOK / TPER), 256>>>(convw);

    // 3) GEMM2: out = y @ w_out^T
    gemm_f16<<<dim3(HIDDEN / BN, NTOK / BM), 128, GSMEM_TOTAL>>>(
        y, w2, out, HIDDEN, 0, nullptr);
}

// round 13
// speedup vs baseline: 7.8899x; 1.0078x over previous
#include <cuda_runtime.h>
#include <cuda_fp16.h>
#include <stdint.h>

#define NUM_SEQS 4
#define SEQ_LEN  4096
#define NTOK     16384
#define HIDDEN   2048
#define CONV_DIM 2048
#define KSZ      4
#define BCX_COLS 6144
#define KDIM     2048

// ---------------- scratch (static device globals; allocation-free) ----------
__device__ __half g_bxh[(size_t)NTOK * CONV_DIM];    // gated input b*x (fp16)
__device__ __half g_ch[(size_t)NTOK * CONV_DIM];     // c gate (fp16)
__device__ __half g_ha[(size_t)NTOK * KDIM];         // fp16 hidden
__device__ __half g_w1p[(size_t)BCX_COLS * KDIM];    // fp16 w_in, rows permuted:
                                                     //  [0,4096): interleaved b,x ; [4096,6144): c
__device__ __half g_w2[(size_t)HIDDEN * KDIM];       // fp16 w_out
__device__ __half g_y[(size_t)NTOK * KDIM];          // fp16 y

// ---------------- ptx helpers (baseline ISA only) ----------------------------
__device__ __forceinline__ uint32_t smem_u32(const void* p) {
    uint32_t a;
    asm("{ .reg .u64 t; cvta.to.shared.u64 t, %1; cvt.u32.u64 %0, t; }" : "=r"(a) : "l"(p));
    return a;
}
__device__ __forceinline__ void cpasync16(uint32_t dst, const void* src) {
    asm volatile("cp.async.cg.shared.global [%0], [%1], 16;" :: "r"(dst), "l"(src));
}
__device__ __forceinline__ void cp_commit() { asm volatile("cp.async.commit_group;" ::: "memory"); }
__device__ __forceinline__ void cp_wait2()  { asm volatile("cp.async.wait_group 2;" ::: "memory"); }

#define LDSM4(r, addr)                                                      \
    asm volatile("ldmatrix.sync.aligned.m8n8.x4.shared.b16 {%0,%1,%2,%3}, [%4];" \
        : "=r"((r)[0]), "=r"((r)[1]), "=r"((r)[2]), "=r"((r)[3]) : "r"(addr))

#define MMAF16(acc, a, b0r, b1r)                                            \
    asm volatile("mma.sync.aligned.m16n8k16.row.col.f32.f16.f16.f32 "       \
        "{%0,%1,%2,%3}, {%4,%5,%6,%7}, {%8,%9}, {%0,%1,%2,%3};"             \
        : "+f"((acc)[0]), "+f"((acc)[1]), "+f"((acc)[2]), "+f"((acc)[3])    \
        : "r"((a)[0]), "r"((a)[1]), "r"((a)[2]), "r"((a)[3]),               \
          "r"(b0r), "r"(b1r))

__device__ __forceinline__ uint32_t swz64(uint32_t off) { return off ^ ((off >> 3) & 0x30); }

// ---------------- fp16 GEMM: C = A[M,K] @ B[N,K]^T --------------------------
// CTA 128x128, 4 warps (2x2), warp tile 64x64, BK=32 halves, 4-stage,
// double-buffered register fragments, 2 CTAs/SM.
// mode 0: plain fp32 C
// mode 1: FUSED in_proj: n0 < 4096 -> interleaved (b,x) -> bx fp16 (g_bxh)
//                        + fp32 states; n0 >= 4096 -> c plane fp16 (g_ch).
#define BM 128
#define BN 128
#define BKC 32
#define NC (KDIM / BKC)              // 64
#define OFF_A 0
#define OFF_B 8192
#define STAGE_BYTES 16384
#define GSMEM_TOTAL (4 * STAGE_BYTES)   // 64KB

__global__ __launch_bounds__(128, 2)
void gemm_f16(const __half* __restrict__ A, const __half* __restrict__ B,
              float* __restrict__ C, int ldC, int mode, float* __restrict__ states)
{
    extern __shared__ char smem[];
    const uint32_t sbase = smem_u32(smem);
    const int tid  = threadIdx.x;
    const int lane = tid & 31;
    const int wid  = tid >> 5;
    const int wm   = wid >> 1;
    const int wn   = wid & 1;
    const int m0 = blockIdx.y * BM;
    const int n0 = blockIdx.x * BN;

    const __half* gA = A + (size_t)m0 * KDIM;
    const __half* gB = B + (size_t)n0 * KDIM;

    uint32_t aRow[4], aXor[4];
#pragma unroll
    for (int mt = 0; mt < 4; mt++) {
        uint32_t r = wm * 64 + mt * 16 + (lane & 15);
        aRow[mt] = r * 64;
        aXor[mt] = (aRow[mt] >> 3) & 0x30;
    }
    const uint32_t aS = (lane >> 4);
    uint32_t bRow[4], bXor[4];
#pragma unroll
    for (int p = 0; p < 4; p++) {
        uint32_t r = wn * 64 + p * 16 + (lane & 7) + ((lane >> 4) << 3);
        bRow[p] = r * 64;
        bXor[p] = (bRow[p] >> 3) & 0x30;
    }
    const uint32_t bS = ((lane >> 3) & 1);

    float acc[4][8][4];
#pragma unroll
    for (int i = 0; i < 4; i++)
#pragma unroll
        for (int j = 0; j < 8; j++)
#pragma unroll
            for (int q = 0; q < 4; q++) acc[i][j][q] = 0.0f;

    auto load_chunk = [&](int c, int st) {
        const uint32_t stg = sbase + st * STAGE_BYTES;
        const int koff = c * BKC;
#pragma unroll
        for (int p = 0; p < 4; p++) {
            int u = p * 128 + tid;
            int r = u >> 2, s = u & 3;
            cpasync16(stg + OFF_A + swz64((uint32_t)(r * 64 + s * 16)),
                      gA + (size_t)r * KDIM + koff + s * 8);
        }
#pragma unroll
        for (int p = 0; p < 4; p++) {
            int u = p * 128 + tid;
            int r = u >> 2, s = u & 3;
            cpasync16(stg + OFF_B + swz64((uint32_t)(r * 64 + s * 16)),
                      gB + (size_t)r * KDIM + koff + s * 8);
        }
    };

    uint32_t af0[4][4], bf0[4][4], af1[4][4], bf1[4][4];

    auto ldsm_set = [&](uint32_t stg, int q, uint32_t af[4][4], uint32_t bf[4][4]) {
        const uint32_t s_a = (q * 2 + aS) * 16;
        const uint32_t s_b = (q * 2 + bS) * 16;
#pragma unroll
        for (int mt = 0; mt < 4; mt++)
            LDSM4(af[mt], stg + OFF_A + aRow[mt] + (s_a ^ aXor[mt]));
#pragma unroll
        for (int p = 0; p < 4; p++)
            LDSM4(bf[p], stg + OFF_B + bRow[p] + (s_b ^ bXor[p]));
    };

    auto mma_set = [&](uint32_t af[4][4], uint32_t bf[4][4]) {
#pragma unroll
        for (int mt = 0; mt < 4; mt++) {
#pragma unroll
            for (int nt = 0; nt < 8; nt++) {
                const int p = nt >> 1, bi = (nt & 1) * 2;
                MMAF16(acc[mt][nt], af[mt], bf[p][bi], bf[p][bi + 1]);
            }
        }
    };

    // prologue: stages 0,1,2
    load_chunk(0, 0); cp_commit();
    load_chunk(1, 1); cp_commit();
    load_chunk(2, 2); cp_commit();
    cp_wait2();
    __syncthreads();
    ldsm_set(sbase, 0, af0, bf0);

    for (int ch = 0; ch < NC; ch++) {
        const uint32_t stg = sbase + (ch & 3) * STAGE_BYTES;
        if (ch + 3 < NC) load_chunk(ch + 3, (ch + 3) & 3);
        cp_commit();

        ldsm_set(stg, 1, af1, bf1);
        mma_set(af0, bf0);
        mma_set(af1, bf1);

        cp_wait2();
        __syncthreads();
        if (ch + 1 < NC)
            ldsm_set(sbase + ((ch + 1) & 3) * STAGE_BYTES, 0, af0, bf0);
    }

    if (mode == 0) {
        const int rw = m0 + wm * 64 + (lane >> 2);
        const int cw = n0 + wn * 64 + (lane & 3) * 2;
#pragma unroll
        for (int mt = 0; mt < 4; mt++) {
#pragma unroll
            for (int nt = 0; nt < 8; nt++) {
                float* p0 = C + (size_t)(rw + mt * 16) * ldC + cw + nt * 8;
                float* p1 = C + (size_t)(rw + mt * 16 + 8) * ldC + cw + nt * 8;
                *(float2*)p0 = make_float2(acc[mt][nt][0], acc[mt][nt][1]);
                *(float2*)p1 = make_float2(acc[mt][nt][2], acc[mt][nt][3]);
            }
        }
    } else if (n0 < 4096) {
        // interleaved (b,x): acc cols (2i, 2i+1) = (b_i, x_i); bx col = i
        const int rw0  = m0 + wm * 64 + (lane >> 2);
        const int colb = (n0 >> 1) + wn * 32 + (lane & 3);
#pragma unroll
        for (int mt = 0; mt < 4; mt++) {
#pragma unroll
            for (int nt = 0; nt < 8; nt++) {
                int col = colb + nt * 4;
                int r0 = rw0 + mt * 16;
                int r1 = r0 + 8;
                float p0 = acc[mt][nt][0] * acc[mt][nt][1];
                float p1 = acc[mt][nt][2] * acc[mt][nt][3];
                g_bxh[(size_t)r0 * CONV_DIM + col] = __float2half_rn(p0);
                g_bxh[(size_t)r1 * CONV_DIM + col] = __float2half_rn(p1);
                int pos0 = r0 & (SEQ_LEN - 1);
                if (pos0 >= SEQ_LEN - (KSZ - 1))
                    states[((size_t)(r0 >> 12) * (KSZ - 1) + (pos0 - (SEQ_LEN - 3))) * CONV_DIM + col] = p0;
                int pos1 = r1 & (SEQ_LEN - 1);
                if (pos1 >= SEQ_LEN - (KSZ - 1))
                    states[((size_t)(r1 >> 12) * (KSZ - 1) + (pos1 - (SEQ_LEN - 3))) * CONV_DIM + col] = p1;
            }
        }
    } else {
        // c plane -> fp16 g_ch, col = n0 - 4096
        const int rw = m0 + wm * 64 + (lane >> 2);
        const int cw = (n0 - 4096) + wn * 64 + (lane & 3) * 2;
#pragma unroll
        for (int mt = 0; mt < 4; mt++) {
#pragma unroll
            for (int nt = 0; nt < 8; nt++) {
                __half2* p0 = (__half2*)&g_ch[(size_t)(rw + mt * 16) * CONV_DIM + cw + nt * 8];
                __half2* p1 = (__half2*)&g_ch[(size_t)(rw + mt * 16 + 8) * CONV_DIM + cw + nt * 8];
                *p0 = __floats2half2_rn(acc[mt][nt][0], acc[mt][nt][1]);
                *p1 = __floats2half2_rn(acc[mt][nt][2], acc[mt][nt][3]);
            }
        }
    }
}

// ---------------- fused fp32 -> fp16 converts (hidden | w_in permuted | w_out)
#define N4_HA (NTOK * KDIM / 4)
#define N4_W1 (BCX_COLS * KDIM / 4)
#define N4_W2 (HIDDEN * KDIM / 4)

__global__ __launch_bounds__(256)
void cvt_all_kernel(const float* __restrict__ hidden, const float* __restrict__ w_in,
                    const float* __restrict__ w_out)
{
    int i = blockIdx.x * blockDim.x + threadIdx.x;
    const float* src;
    __half* dst;
    int j;
    if (i < N4_HA) {
        j = i; src = hidden; dst = g_ha;
    } else if (i < N4_HA + N4_W1) {
        j = i - N4_HA;
        int r = (j * 4) / KDIM, k = (j * 4) % KDIM;
        int sr = (r < 4096) ? ((r >> 1) + ((r & 1) ? 4096 : 0)) : (r - 2048);
        float4 v = *(const float4*)(w_in + (size_t)sr * KDIM + k);
        ((__half2*)g_w1p)[j * 2 + 0] = __floats2half2_rn(v.x, v.y);
        ((__half2*)g_w1p)[j * 2 + 1] = __floats2half2_rn(v.z, v.w);
        return;
    } else if (i < N4_HA + N4_W1 + N4_W2) {
        j = i - N4_HA - N4_W1; src = w_out; dst = g_w2;
    } else return;
    float4 v = ((const float4*)src)[j];
    ((__half2*)dst)[j * 2 + 0] = __floats2half2_rn(v.x, v.y);
    ((__half2*)dst)[j * 2 + 1] = __floats2half2_rn(v.z, v.w);
}

// ---------------- causal conv + BCx gate, 2 channels/thread (all fp16) ------
#define TPER 8
#define DPAIRS (CONV_DIM / 2)   // 1024

__global__ __launch_bounds__(256)
void conv_gate_kernel(const float* __restrict__ cw)
{
    int dp = blockIdx.x * blockDim.x + threadIdx.x;  // channel pair 0..1023
    int t0 = blockIdx.y * TPER;
    int pos0 = t0 & (SEQ_LEN - 1);

    const __half2* bxp = (const __half2*)g_bxh;
    const __half2* chp = (const __half2*)g_ch;
    __half2* yp = (__half2*)g_y;

    float4 wa = *(const float4*)(cw + dp * 8);       // channel 2*dp
    float4 wb = *(const float4*)(cw + dp * 8 + 4);   // channel 2*dp+1

    float2 h0 = {0.f, 0.f}, h1 = {0.f, 0.f}, h2 = {0.f, 0.f};
    if (pos0 >= 3) h0 = __half22float2(bxp[(size_t)(t0 - 3) * DPAIRS + dp]);
    if (pos0 >= 2) h1 = __half22float2(bxp[(size_t)(t0 - 2) * DPAIRS + dp]);
    if (pos0 >= 1) h2 = __half22float2(bxp[(size_t)(t0 - 1) * DPAIRS + dp]);

#pragma unroll
    for (int i = 0; i < TPER; i++) {
        size_t idx = (size_t)(t0 + i) * DPAIRS + dp;
        float2 bx = __half22float2(bxp[idx]);
        float cx = fmaf(wa.x, h0.x, fmaf(wa.y, h1.x, fmaf(wa.z, h2.x, wa.w * bx.x)));
        float cy = fmaf(wb.x, h0.y, fmaf(wb.y, h1.y, fmaf(wb.z, h2.y, wb.w * bx.y)));
        float2 c = __half22float2(chp[idx]);
        yp[idx] = __floats2half2_rn(c.x * cx, c.y * cy);
        h0 = h1; h1 = h2; h2 = bx;
    }
}

// ---------------- launch -----------------------------------------------------
extern "C" void kernel_launch(void* const* d_in, const int* in_sizes, int n_in,
                              void* d_out, int out_size)
{
    const float* hidden = (const float*)d_in[0];
    const float* w_in   = (const float*)d_in[1];
    const float* convw  = (const float*)d_in[2];
    const float* w_out  = (const float*)d_in[3];
    float* out = (float*)d_out;
    float* states = out + (size_t)NTOK * HIDDEN;

    __half *ha, *w1p, *w2, *y;
    cudaGetSymbolAddress((void**)&ha,  g_ha);
    cudaGetSymbolAddress((void**)&w1p, g_w1p);
    cudaGetSymbolAddress((void**)&w2,  g_w2);
    cudaGetSymbolAddress((void**)&y,   g_y);

    cudaFuncSetAttribute(gemm_f16, cudaFuncAttributeMaxDynamicSharedMemorySize, GSMEM_TOTAL);

    // 0) fused fp16 conversions
    {
        int total = N4_HA + N4_W1 + N4_W2;
        cvt_all_kernel<<<(total + 255) / 256, 256>>>(hidden, w_in, w_out);
    }

    // 1) FUSED in_proj GEMM: bx=b*x fp16 (+fp32 states) AND c-plane fp16
    gemm_f16<<<dim3(BCX_COLS / BN, NTOK / BM), 128, GSMEM_TOTAL>>>(
        ha, w1p, nullptr, CONV_DIM, 1, states);

    // 2) conv + BCx gate -> y (fp16), 2 channels per thread
    conv_gate_kernel<<<dim3(DPAIRS / 256, NTOK / TPER), 256>>>(convw);

    // 3) GEMM2: out = y @ w_out^T
    gemm_f16<<<dim3(HIDDEN / BN, NTOK / BM), 128, GSMEM_TOTAL>>>(
        y, w2, out, HIDDEN, 0, nullptr);
}